// round 4
// baseline (speedup 1.0000x reference)
#include <cuda_runtime.h>
#include <cuda_bf16.h>
#include <math.h>
#include <stdint.h>

// Problem constants
#define BB    64
#define LL    512
#define DDIM  512
#define HH    8
#define EE    64
#define DFF   2048
#define NMODES 32
#define NAPP  10000
#define KCAT  536    // D + 24
#define MTOT  (BB*LL)
#define TWOPI 6.283185307179586476925286766559

// ---------------------------------------------------------------------------
// Scratch (device globals — no runtime allocation allowed)
// ---------------------------------------------------------------------------
__device__ __align__(128) float g_x [MTOT*DDIM];
__device__ __align__(128) float g_q [MTOT*DDIM];
__device__ __align__(128) float g_t2[MTOT*DDIM];
__device__ __align__(128) float g_cat[BB*KCAT];

// activation bf16 hi/lo planes
__device__ __align__(128) __nv_bfloat16 g_pah[MTOT*DDIM], g_pal[MTOT*DDIM];
__device__ __align__(128) __nv_bfloat16 g_yph[MTOT*DFF],  g_ypl[MTOT*DFF];

// weight / twiddle bf16 hi/lo planes
__device__ __align__(128) __nv_bfloat16 g_wqh[2*DDIM*DDIM], g_wql[2*DDIM*DDIM];
__device__ __align__(128) __nv_bfloat16 g_woh[2*DDIM*DDIM], g_wol[2*DDIM*DDIM];
__device__ __align__(128) __nv_bfloat16 g_c1h[2*DFF*DDIM],  g_c1l[2*DFF*DDIM];
__device__ __align__(128) __nv_bfloat16 g_c2h[2*DDIM*DFF],  g_c2l[2*DDIM*DFF];
__device__ __align__(128) __nv_bfloat16 g_twh[128*512],     g_twl[128*512];   // fwd DFT (padded 128 rows)
__device__ __align__(128) __nv_bfloat16 g_itwh[512*64],     g_itwl[512*64];   // inv DFT

// ---------------------------------------------------------------------------
// PTX helpers (arch-portable: ldmatrix / mma.sync / cp.async only)
// ---------------------------------------------------------------------------
__device__ __forceinline__ uint32_t smem_u32(const void* p) {
    uint32_t a;
    asm("{ .reg .u64 t; cvta.to.shared.u64 t, %1; cvt.u32.u64 %0, t; }" : "=r"(a) : "l"(p));
    return a;
}
#define CP16(d, s)  asm volatile("cp.async.cg.shared.global [%0], [%1], 16;" :: "r"(d), "l"(s) : "memory")
#define CP_COMMIT() asm volatile("cp.async.commit_group;" ::: "memory")
#define CP_WAIT0()  asm volatile("cp.async.wait_group 0;" ::: "memory")

#define LDSM4(r0, r1, r2, r3, a) \
    asm volatile("ldmatrix.sync.aligned.m8n8.x4.shared.b16 {%0,%1,%2,%3}, [%4];" \
        : "=r"(r0), "=r"(r1), "=r"(r2), "=r"(r3) : "r"(a))

#define MMA16816(c, a0, a1, a2, a3, b0, b1) \
    asm volatile("mma.sync.aligned.m16n8k16.row.col.f32.bf16.bf16.f32 " \
        "{%0,%1,%2,%3}, {%4,%5,%6,%7}, {%8,%9}, {%0,%1,%2,%3};" \
        : "+f"((c)[0]), "+f"((c)[1]), "+f"((c)[2]), "+f"((c)[3]) \
        : "r"(a0), "r"(a1), "r"(a2), "r"(a3), "r"(b0), "r"(b1))

__device__ __forceinline__ void split2(float v, __nv_bfloat16& h, __nv_bfloat16& l) {
    h = __float2bfloat16(v);
    l = __float2bfloat16(v - __bfloat162float(h));
}

// ---------------------------------------------------------------------------
// Tensor-core GEMM: C[m,n] = sum_k A[m,k]*B[n,k]  (+bias) (+Cin) (relu)
//   A, B both pre-split bf16 hi/lo planes [.,K]. Split-3: AhBh + AlBh + AhBl.
//   Tile 128xBN, BK=32, 256 threads, double-buffered cp.async.
//   SMEM rows at 80B pitch -> conflict-free ldmatrix. K mult of 32.
//   Output: f32 C (stride Nout) or bf16 hi/lo planes Oh/Ol.
// ---------------------------------------------------------------------------
template <int BN, int RELU, int ADDC, int BIAS, int OUTPL>
__global__ void __launch_bounds__(256, 1)
mgemm_k(const __nv_bfloat16* __restrict__ Ah, const __nv_bfloat16* __restrict__ Al,
        const __nv_bfloat16* __restrict__ Bh, const __nv_bfloat16* __restrict__ Bl,
        const float* __restrict__ bias, const float* __restrict__ Cin,
        float* __restrict__ C, __nv_bfloat16* __restrict__ Oh,
        __nv_bfloat16* __restrict__ Ol, int K, int Nout) {
    constexpr int PLA = 128 * 80;
    constexpr int PLB = BN * 80;
    constexpr int STAGE = 2 * PLA + 2 * PLB;
    constexpr int OAH = 0, OAL = PLA, OBH = 2 * PLA, OBL = 2 * PLA + PLB;
    constexpr int WN = BN / 2;       // cols per warp
    constexpr int NP = WN / 16;      // 16-col fragment groups per warp

    extern __shared__ __align__(128) char smem[];
    const uint32_t sb = smem_u32(smem);
    const int tid = threadIdx.x, lane = tid & 31, wid = tid >> 5;
    const int wm = wid & 3, wn = wid >> 2;       // warps 4 x 2
    const int m0 = blockIdx.y * 128, n0 = blockIdx.x * BN;

    float acc[2][2 * NP][4];
#pragma unroll
    for (int i = 0; i < 2; i++)
#pragma unroll
        for (int j = 0; j < 2 * NP; j++)
#pragma unroll
            for (int t = 0; t < 4; t++) acc[i][j][t] = 0.f;

    const uint32_t a_off = (uint32_t)((wm * 32 + (lane & 7) + ((lane >> 3) & 1) * 8) * 80
                                      + (lane >> 4) * 16);
    const uint32_t b_off = (uint32_t)((wn * WN + ((lane >> 4) & 1) * 8 + (lane & 7)) * 80
                                      + ((lane >> 3) & 1) * 16);

    auto cpAB = [&](int c, int s) {
        const uint32_t base = sb + s * STAGE;
#pragma unroll
        for (int j = 0; j < 4; j++) {            // A: 1024 x 16B
            int idx = j * 256 + tid;
            int pl = idx >> 9;
            int r = (idx >> 2) & 127, ch = idx & 3;
            const __nv_bfloat16* src = (pl ? Al : Ah) + (size_t)(m0 + r) * K + c * 32 + ch * 8;
            CP16(base + (pl ? OAL : OAH) + (uint32_t)(r * 80 + ch * 16), src);
        }
#pragma unroll
        for (int j = 0; j < BN / 32; j++) {      // B: BN*8 x 16B
            int idx = j * 256 + tid;
            int pl = (idx >= 4 * BN) ? 1 : 0;
            int rem = idx - pl * 4 * BN;
            int r = rem >> 2, ch = rem & 3;
            const __nv_bfloat16* src = (pl ? Bl : Bh) + (size_t)(n0 + r) * K + c * 32 + ch * 8;
            CP16(base + (pl ? OBL : OBH) + (uint32_t)(r * 80 + ch * 16), src);
        }
        CP_COMMIT();
    };

    const int NC = K >> 5;
    cpAB(0, 0);
    for (int c = 0; c < NC; c++) {
        const int s = c & 1;
        CP_WAIT0();
        __syncthreads();
        if (c + 1 < NC) cpAB(c + 1, s ^ 1);      // overlaps compute below
        const uint32_t base = sb + s * STAGE;
#pragma unroll
        for (int ks = 0; ks < 2; ks++) {
            const uint32_t koff = ks * 32;
            uint32_t ah[2][4], al[2][4];
#pragma unroll
            for (int mi = 0; mi < 2; mi++) {
                LDSM4(ah[mi][0], ah[mi][1], ah[mi][2], ah[mi][3],
                      base + OAH + a_off + mi * (16 * 80) + koff);
                LDSM4(al[mi][0], al[mi][1], al[mi][2], al[mi][3],
                      base + OAL + a_off + mi * (16 * 80) + koff);
            }
#pragma unroll
            for (int np = 0; np < NP; np++) {
                uint32_t bh[4], bl[4];
                LDSM4(bh[0], bh[1], bh[2], bh[3],
                      base + OBH + b_off + np * (16 * 80) + koff);
                LDSM4(bl[0], bl[1], bl[2], bl[3],
                      base + OBL + b_off + np * (16 * 80) + koff);
#pragma unroll
                for (int mi = 0; mi < 2; mi++) {
#pragma unroll
                    for (int t = 0; t < 2; t++) {
                        float* cc = acc[mi][np * 2 + t];
                        MMA16816(cc, ah[mi][0], ah[mi][1], ah[mi][2], ah[mi][3],
                                 bh[2*t], bh[2*t + 1]);
                        MMA16816(cc, al[mi][0], al[mi][1], al[mi][2], al[mi][3],
                                 bh[2*t], bh[2*t + 1]);
                        MMA16816(cc, ah[mi][0], ah[mi][1], ah[mi][2], ah[mi][3],
                                 bl[2*t], bl[2*t + 1]);
                    }
                }
            }
        }
    }

    // epilogue
#pragma unroll
    for (int mi = 0; mi < 2; mi++) {
        const int r0 = m0 + wm * 32 + mi * 16 + (lane >> 2);
#pragma unroll
        for (int ni = 0; ni < 2 * NP; ni++) {
            const int col = n0 + wn * WN + ni * 8 + 2 * (lane & 3);
            if (col >= Nout) continue;
            float v00 = acc[mi][ni][0], v01 = acc[mi][ni][1];
            float v10 = acc[mi][ni][2], v11 = acc[mi][ni][3];
            if (BIAS) {
                float2 bv = *(const float2*)&bias[col];
                v00 += bv.x; v01 += bv.y; v10 += bv.x; v11 += bv.y;
            }
            const size_t o0 = (size_t)r0 * Nout + col;
            const size_t o1 = (size_t)(r0 + 8) * Nout + col;
            if (ADDC) {
                float2 c0 = *(const float2*)&Cin[o0];
                float2 c1 = *(const float2*)&Cin[o1];
                v00 += c0.x; v01 += c0.y; v10 += c1.x; v11 += c1.y;
            }
            if (RELU) {
                v00 = fmaxf(v00, 0.f); v01 = fmaxf(v01, 0.f);
                v10 = fmaxf(v10, 0.f); v11 = fmaxf(v11, 0.f);
            }
            if (OUTPL) {
                __nv_bfloat162 h0, l0, h1, l1;
                split2(v00, h0.x, l0.x); split2(v01, h0.y, l0.y);
                split2(v10, h1.x, l1.x); split2(v11, h1.y, l1.y);
                *(__nv_bfloat162*)&Oh[o0] = h0;
                *(__nv_bfloat162*)&Ol[o0] = l0;
                *(__nv_bfloat162*)&Oh[o1] = h1;
                *(__nv_bfloat162*)&Ol[o1] = l1;
            } else {
                *(float2*)&C[o0] = make_float2(v00, v01);
                *(float2*)&C[o1] = make_float2(v10, v11);
            }
        }
    }
}

template <int BN, int R, int AD, int BI, int OP>
static void mg2(const __nv_bfloat16* Ah, const __nv_bfloat16* Al,
                const __nv_bfloat16* Bh, const __nv_bfloat16* Bl,
                const float* bias, const float* Cin, float* C,
                __nv_bfloat16* Oh, __nv_bfloat16* Ol,
                int M, int Npad, int K, int Nout) {
    constexpr int SMEM = 2 * (2 * 128 * 80 + 2 * BN * 80);
    cudaFuncSetAttribute(mgemm_k<BN, R, AD, BI, OP>,
                         cudaFuncAttributeMaxDynamicSharedMemorySize, SMEM);
    dim3 g(Npad / BN, M / 128);
    mgemm_k<BN, R, AD, BI, OP><<<g, 256, SMEM>>>(Ah, Al, Bh, Bl, bias, Cin, C, Oh, Ol, K, Nout);
}

// ---------------------------------------------------------------------------
// Weight split + twiddle init
// ---------------------------------------------------------------------------
__global__ void split_k(const float* __restrict__ s, __nv_bfloat16* __restrict__ h,
                        __nv_bfloat16* __restrict__ l, int n) {
    int i = blockIdx.x * blockDim.x + threadIdx.x;
    if (i < n) split2(s[i], h[i], l[i]);
}

__global__ void init_tw_k(__nv_bfloat16* twh, __nv_bfloat16* twl,
                          __nv_bfloat16* itwh, __nv_bfloat16* itwl) {
    int i = blockIdx.x * blockDim.x + threadIdx.x;   // 0..65535
    {
        int c = i >> 9, l = i & 511;
        double v = 0.0;
        if (c < 32)       v = cos((TWOPI / 512.0) * (double)(l * c));
        else if (c < 64)  v = -sin((TWOPI / 512.0) * (double)(l * (c - 32)));
        split2((float)v, twh[i], twl[i]);
    }
    if (i < 512 * 64) {
        int l = i >> 6, c = i & 63;
        double v;
        if (c == 0)       v = 1.0 / 512.0;
        else if (c < 32)  v = 2.0 * cos((TWOPI / 512.0) * (double)(l * c)) / 512.0;
        else if (c == 32) v = 0.0;
        else              v = -2.0 * sin((TWOPI / 512.0) * (double)(l * (c - 32))) / 512.0;
        split2((float)v, itwh[i], itwl[i]);
    }
}

// ---------------------------------------------------------------------------
// Embedding (writes f32 + planes)
// ---------------------------------------------------------------------------
__global__ void embed_k(const int* __restrict__ x_app, const float* __restrict__ x_time,
                        const float* __restrict__ emb, const float* __restrict__ tw,
                        const float* __restrict__ tb, float* __restrict__ x,
                        __nv_bfloat16* __restrict__ ph, __nv_bfloat16* __restrict__ po) {
    int b = blockIdx.y, l = blockIdx.x, d = threadIdx.x;
    int a = x_app[b * LL + l];
    float t = x_time[b * LL + l];
    size_t idx = ((size_t)b * LL + l) * DDIM + d;
    float v = emb[(size_t)a * DDIM + d] + t * tw[d] + tb[d];
    x[idx] = v;
    split2(v, ph[idx], po[idx]);
}

// ---------------------------------------------------------------------------
// fp32 SIMT GEMM (final projection only: K=536)
// ---------------------------------------------------------------------------
__global__ __launch_bounds__(256, 2)
void gemm_nt_kernel(const float* __restrict__ A, const float* __restrict__ Bm,
                    const float* __restrict__ bias, float* __restrict__ Cout,
                    int M, int N, int K) {
    __shared__ float As[8][128];
    __shared__ float Bs[8][128];
    const int tid = threadIdx.x;
    const int m0 = blockIdx.y * 128, n0 = blockIdx.x * 128;
    const int lr = tid >> 1, lk = (tid & 1) * 4;
    const int tx = tid & 15, ty = tid >> 4;
    const int arow = m0 + lr, brow = n0 + lr;
    const bool aval = arow < M, bval = brow < N;
    const float* Ap = A + (size_t)arow * K + lk;
    const float* Bp = Bm + (size_t)brow * K + lk;
    float acc[8][8];
#pragma unroll
    for (int i = 0; i < 8; i++)
#pragma unroll
        for (int j = 0; j < 8; j++) acc[i][j] = 0.f;
    const float4 z4 = make_float4(0.f, 0.f, 0.f, 0.f);
    for (int k0 = 0; k0 < K; k0 += 8) {
        float4 a = z4, b = z4;
        if (aval && lk + k0 < K) a = *(const float4*)Ap;
        if (bval && lk + k0 < K) b = *(const float4*)Bp;
        Ap += 8; Bp += 8;
        __syncthreads();
        As[lk+0][lr]=a.x; As[lk+1][lr]=a.y; As[lk+2][lr]=a.z; As[lk+3][lr]=a.w;
        Bs[lk+0][lr]=b.x; Bs[lk+1][lr]=b.y; Bs[lk+2][lr]=b.z; Bs[lk+3][lr]=b.w;
        __syncthreads();
#pragma unroll
        for (int k = 0; k < 8; k++) {
            float arv[8], brv[8];
            *(float4*)&arv[0] = *(const float4*)&As[k][ty*8];
            *(float4*)&arv[4] = *(const float4*)&As[k][ty*8+4];
            *(float4*)&brv[0] = *(const float4*)&Bs[k][tx*8];
            *(float4*)&brv[4] = *(const float4*)&Bs[k][tx*8+4];
#pragma unroll
            for (int i = 0; i < 8; i++)
#pragma unroll
                for (int j = 0; j < 8; j++) acc[i][j] += arv[i] * brv[j];
        }
    }
#pragma unroll
    for (int i = 0; i < 8; i++) {
        int m = m0 + ty * 8 + i;
        if (m >= M) continue;
        size_t row = (size_t)m * N;
#pragma unroll
        for (int jg = 0; jg < 8; jg++) {
            int n = n0 + tx * 8 + jg;
            if (n >= N) continue;
            Cout[row + n] = acc[i][jg] + bias[n];
        }
    }
}

// ---------------------------------------------------------------------------
// Per-batch 512x512 transpose: f32 in -> bf16 hi/lo planes out (transposed)
// ---------------------------------------------------------------------------
__global__ void transpose_split_k(const float* __restrict__ in,
                                  __nv_bfloat16* __restrict__ ph,
                                  __nv_bfloat16* __restrict__ po) {
    __shared__ float tile[32][33];
    int b = blockIdx.z;
    const float* ip = in + (size_t)b * (512 * 512);
    int i0 = blockIdx.y * 32, j0 = blockIdx.x * 32;
#pragma unroll
    for (int r = 0; r < 32; r += 8)
        tile[threadIdx.y + r][threadIdx.x] =
            ip[(size_t)(i0 + threadIdx.y + r) * 512 + j0 + threadIdx.x];
    __syncthreads();
#pragma unroll
    for (int r = 0; r < 32; r += 8) {
        float v = tile[threadIdx.x][threadIdx.y + r];
        size_t o = (size_t)b * (512 * 512) + (size_t)(j0 + threadIdx.y + r) * 512
                   + i0 + threadIdx.x;
        split2(v, ph[o], po[o]);
    }
}

// ---------------------------------------------------------------------------
// Complex mode mixing -> writes bf16 hi/lo planes [M][64]
// ---------------------------------------------------------------------------
__global__ void modemix_k(const float* __restrict__ xs, const float* __restrict__ wr,
                          const float* __restrict__ wi, __nv_bfloat16* __restrict__ ph,
                          __nv_bfloat16* __restrict__ po) {
    int mode = blockIdx.x, h = blockIdx.y;
    __shared__ float Xr[64][32], Xi[64][32], Wr[32][64], Wi[32][64];
    int tid = threadIdx.x;
    int tb = tid >> 4, to = tid & 15;
    float cr[4][4], ci[4][4];
#pragma unroll
    for (int a = 0; a < 4; a++)
#pragma unroll
        for (int c = 0; c < 4; c++) { cr[a][c] = 0.f; ci[a][c] = 0.f; }
    for (int i0 = 0; i0 < 64; i0 += 32) {
#pragma unroll
        for (int j = 0; j < 8; j++) {
            int e = tid * 8 + j;
            int b = e >> 5, ii = e & 31;
            size_t xrow = ((size_t)b * 512 + h * 64 + i0 + ii) * 64;
            Xr[b][ii] = xs[xrow + mode];
            Xi[b][ii] = xs[xrow + 32 + mode];
            int wi2 = e >> 6, o = e & 63;
            size_t widx = (((size_t)h * 64 + i0 + wi2) * 64 + o) * 32 + mode;
            Wr[wi2][o] = wr[widx];
            Wi[wi2][o] = wi[widx];
        }
        __syncthreads();
#pragma unroll 8
        for (int ii = 0; ii < 32; ii++) {
            float xr[4], xi4[4], wrv[4], wiv[4];
#pragma unroll
            for (int a = 0; a < 4; a++) { xr[a] = Xr[tb*4+a][ii]; xi4[a] = Xi[tb*4+a][ii]; }
#pragma unroll
            for (int c = 0; c < 4; c++) { wrv[c] = Wr[ii][to*4+c]; wiv[c] = Wi[ii][to*4+c]; }
#pragma unroll
            for (int a = 0; a < 4; a++)
#pragma unroll
                for (int c = 0; c < 4; c++) {
                    cr[a][c] += xr[a] * wrv[c] - xi4[a] * wiv[c];
                    ci[a][c] += xr[a] * wiv[c] + xi4[a] * wrv[c];
                }
        }
        __syncthreads();
    }
#pragma unroll
    for (int a = 0; a < 4; a++) {
        int b = tb * 4 + a;
#pragma unroll
        for (int c = 0; c < 4; c++) {
            int o = to * 4 + c;
            size_t base = ((size_t)b * 512 + h * 64 + o) * 64;
            split2(cr[a][c], ph[base + mode], po[base + mode]);
            split2(ci[a][c], ph[base + 32 + mode], po[base + 32 + mode]);
        }
    }
}

// ---------------------------------------------------------------------------
// Series decomposition: out = in - moving_avg_25(in); writes f32 + planes
// ---------------------------------------------------------------------------
__global__ void decomp_split_k(const float* __restrict__ in, float* __restrict__ out,
                               __nv_bfloat16* __restrict__ ph, __nv_bfloat16* __restrict__ po) {
    int b = blockIdx.y, l = blockIdx.x, d = threadIdx.x;
    const float* base = in + (size_t)b * (LL * DDIM);
    float s = 0.f;
#pragma unroll
    for (int j = -12; j <= 12; j++) {
        int ll = l + j;
        ll = ll < 0 ? 0 : (ll > 511 ? 511 : ll);
        s += base[(size_t)ll * DDIM + d];
    }
    size_t idx = ((size_t)b * LL + l) * DDIM + d;
    float v = base[(size_t)l * DDIM + d] - s * (1.0f / 25.0f);
    out[idx] = v;
    split2(v, ph[idx], po[idx]);
}

// ---------------------------------------------------------------------------
// LayerNorm + last-token concat
// ---------------------------------------------------------------------------
__device__ __forceinline__ float blocksum512(float v, float* red) {
    int lane = threadIdx.x & 31, w = threadIdx.x >> 5;
#pragma unroll
    for (int o = 16; o; o >>= 1) v += __shfl_down_sync(0xffffffffu, v, o);
    if (lane == 0) red[w] = v;
    __syncthreads();
    if (w == 0) {
        float t = (lane < 16) ? red[lane] : 0.f;
#pragma unroll
        for (int o = 8; o; o >>= 1) t += __shfl_down_sync(0xffffffffu, t, o);
        if (lane == 0) red[0] = t;
    }
    __syncthreads();
    float r = red[0];
    __syncthreads();
    return r;
}

__global__ void layernorm_k(const float* __restrict__ x, const float* __restrict__ w,
                            const float* __restrict__ bb, float* __restrict__ xh) {
    __shared__ float red[32];
    int b = blockIdx.y, l = blockIdx.x, d = threadIdx.x;
    size_t base = ((size_t)b * LL + l) * DDIM;
    float v = x[base + d];
    float mu = blocksum512(v, red) * (1.f / 512.f);
    float dv = v - mu;
    float var = blocksum512(dv * dv, red) * (1.f / 512.f);
    xh[base + d] = dv * rsqrtf(var + 1e-5f) * w[d] + bb[d];
}

__global__ void lastcat_k(const float* __restrict__ xh, const float* __restrict__ time_vecs,
                          float* __restrict__ cat) {
    int b = blockIdx.x, d = threadIdx.x;
    float s = 0.f;
    for (int l = 0; l < LL; l++) s += xh[((size_t)b * LL + l) * DDIM + d];
    cat[b * KCAT + d] = xh[((size_t)b * LL + 511) * DDIM + d] - s * (1.f / 512.f);
    if (d < 24) cat[b * KCAT + 512 + d] = time_vecs[((size_t)b * LL + 511) * 24 + d];
}

// ---------------------------------------------------------------------------
// Host orchestration
// ---------------------------------------------------------------------------
extern "C" void kernel_launch(void* const* d_in, const int* in_sizes, int n_in,
                              void* d_out, int out_size) {
    (void)in_sizes; (void)n_in; (void)out_size;
    const int*   x_app     = (const int*)  d_in[0];
    const float* x_time    = (const float*)d_in[1];
    const float* time_vecs = (const float*)d_in[2];
    const float* emb       = (const float*)d_in[4];
    const float* time_w    = (const float*)d_in[5];
    const float* time_b    = (const float*)d_in[6];
    const float* Wq        = (const float*)d_in[7];
    const float* bq        = (const float*)d_in[8];
    const float* Wo        = (const float*)d_in[9];
    const float* bo        = (const float*)d_in[10];
    const float* four_wr   = (const float*)d_in[11];
    const float* four_wi   = (const float*)d_in[12];
    const float* conv1     = (const float*)d_in[13];
    const float* conv2     = (const float*)d_in[14];
    const float* norm_w    = (const float*)d_in[15];
    const float* norm_b    = (const float*)d_in[16];
    const float* proj_w    = (const float*)d_in[17];
    const float* proj_b    = (const float*)d_in[18];

    float *gx, *gq, *gt2, *gcat;
    __nv_bfloat16 *pah, *pal, *yph, *ypl;
    __nv_bfloat16 *wqh, *wql, *woh, *wol, *c1h, *c1l, *c2h, *c2l, *twh, *twl, *itwh, *itwl;
    cudaGetSymbolAddress((void**)&gx,   g_x);
    cudaGetSymbolAddress((void**)&gq,   g_q);
    cudaGetSymbolAddress((void**)&gt2,  g_t2);
    cudaGetSymbolAddress((void**)&gcat, g_cat);
    cudaGetSymbolAddress((void**)&pah,  g_pah);  cudaGetSymbolAddress((void**)&pal, g_pal);
    cudaGetSymbolAddress((void**)&yph,  g_yph);  cudaGetSymbolAddress((void**)&ypl, g_ypl);
    cudaGetSymbolAddress((void**)&wqh,  g_wqh);  cudaGetSymbolAddress((void**)&wql, g_wql);
    cudaGetSymbolAddress((void**)&woh,  g_woh);  cudaGetSymbolAddress((void**)&wol, g_wol);
    cudaGetSymbolAddress((void**)&c1h,  g_c1h);  cudaGetSymbolAddress((void**)&c1l, g_c1l);
    cudaGetSymbolAddress((void**)&c2h,  g_c2h);  cudaGetSymbolAddress((void**)&c2l, g_c2l);
    cudaGetSymbolAddress((void**)&twh,  g_twh);  cudaGetSymbolAddress((void**)&twl, g_twl);
    cudaGetSymbolAddress((void**)&itwh, g_itwh); cudaGetSymbolAddress((void**)&itwl, g_itwl);

    const int M = MTOT;   // 32768

    init_tw_k<<<256, 256>>>(twh, twl, itwh, itwl);
    split_k<<<(2*DDIM*DDIM + 255)/256, 256>>>(Wq, wqh, wql, 2*DDIM*DDIM);
    split_k<<<(2*DDIM*DDIM + 255)/256, 256>>>(Wo, woh, wol, 2*DDIM*DDIM);
    split_k<<<(2*DFF*DDIM + 255)/256, 256>>>(conv1, c1h, c1l, 2*DFF*DDIM);
    split_k<<<(2*DDIM*DFF + 255)/256, 256>>>(conv2, c2h, c2l, 2*DDIM*DFF);

    embed_k<<<dim3(LL, BB), DDIM>>>(x_app, x_time, emb, time_w, time_b, gx, pah, pal);

    dim3 tgrid(16, 16, BB), tblk(32, 8);
    for (int l = 0; l < 2; l++) {
        const float* bql = bq + (size_t)l * DDIM;
        const float* bol = bo + (size_t)l * DDIM;
        const float* wrl = four_wr + (size_t)l * HH * EE * EE * NMODES;
        const float* wil = four_wi + (size_t)l * HH * EE * EE * NMODES;
        size_t owq = (size_t)l * DDIM * DDIM;
        size_t oc1 = (size_t)l * DFF * DDIM;
        size_t oc2 = (size_t)l * DDIM * DFF;

        // q = x @ Wq^T + bq  (f32 out)
        mg2<256,0,0,1,0>(pah, pal, wqh + owq, wql + owq, bql, nullptr, gq,
                         nullptr, nullptr, M, 512, 512, 512);
        // qT planes
        transpose_split_k<<<tgrid, tblk>>>(gq, pah, pal);
        // forward DFT: xs = qT @ TW^T  (Nout=64, f32)
        mg2<128,0,0,0,0>(pah, pal, twh, twl, nullptr, nullptr, gt2,
                         nullptr, nullptr, M, 128, 512, 64);
        // complex mode mixing -> g planes [M][64]
        modemix_k<<<dim3(NMODES, HH), 256>>>(gt2, wrl, wil, pah, pal);
        // inverse DFT: foutT = g @ ITW^T (f32)
        mg2<256,0,0,0,0>(pah, pal, itwh, itwl, nullptr, nullptr, gq,
                         nullptr, nullptr, M, 512, 64, 512);
        // fout planes
        transpose_split_k<<<tgrid, tblk>>>(gq, pah, pal);
        // tmp = fout @ Wo^T + bo + x  (f32)
        mg2<256,0,1,1,0>(pah, pal, woh + owq, wol + owq, bol, gx, gt2,
                         nullptr, nullptr, M, 512, 512, 512);
        // x = tmp - movavg(tmp)  (f32 + planes)
        decomp_split_k<<<dim3(LL, BB), DDIM>>>(gt2, gx, pah, pal);
        // y = relu(x @ c1^T)  (planes out only)
        mg2<256,1,0,0,1>(pah, pal, c1h + oc1, c1l + oc1, nullptr, nullptr, nullptr,
                         yph, ypl, M, 2048, 512, 2048);
        // tmp = y @ c2^T + x  (f32)
        mg2<256,0,1,0,0>(yph, ypl, c2h + oc2, c2l + oc2, nullptr, gx, gt2,
                         nullptr, nullptr, M, 512, 2048, 512);
        // x = tmp - movavg(tmp)
        decomp_split_k<<<dim3(LL, BB), DDIM>>>(gt2, gx, pah, pal);
    }

    layernorm_k<<<dim3(LL, BB), DDIM>>>(gx, norm_w, norm_b, gq);
    lastcat_k<<<BB, DDIM>>>(gq, time_vecs, gcat);
    gemm_nt_kernel<<<dim3((NAPP + 127) / 128, 1), 256>>>(gcat, proj_w, proj_b,
                                                         (float*)d_out, BB, NAPP, KCAT);
}

// round 5
// speedup vs baseline: 1.0571x; 1.0571x over previous
#include <cuda_runtime.h>
#include <cuda_bf16.h>
#include <math.h>
#include <stdint.h>

// Problem constants
#define BB    64
#define LL    512
#define DDIM  512
#define HH    8
#define EE    64
#define DFF   2048
#define NMODES 32
#define NAPP  10000
#define KCAT  536    // D + 24
#define MTOT  (BB*LL)
#define TWOPI 6.283185307179586476925286766559

// ---------------------------------------------------------------------------
// Scratch (device globals — no runtime allocation allowed)
// ---------------------------------------------------------------------------
__device__ __align__(128) float g_x [MTOT*DDIM];
__device__ __align__(128) float g_q [MTOT*DDIM];
__device__ __align__(128) float g_t2[MTOT*DDIM];
__device__ __align__(128) float g_cat[BB*KCAT];

// activation bf16 hi/lo planes
__device__ __align__(128) __nv_bfloat16 g_pah[MTOT*DDIM], g_pal[MTOT*DDIM];
__device__ __align__(128) __nv_bfloat16 g_yph[MTOT*DFF],  g_ypl[MTOT*DFF];

// weight / twiddle bf16 hi/lo planes
__device__ __align__(128) __nv_bfloat16 g_wqh[2*DDIM*DDIM], g_wql[2*DDIM*DDIM];
__device__ __align__(128) __nv_bfloat16 g_woh[2*DDIM*DDIM], g_wol[2*DDIM*DDIM];
__device__ __align__(128) __nv_bfloat16 g_c1h[2*DFF*DDIM],  g_c1l[2*DFF*DDIM];
__device__ __align__(128) __nv_bfloat16 g_c2h[2*DDIM*DFF],  g_c2l[2*DDIM*DFF];
__device__ __align__(128) __nv_bfloat16 g_twh[128*512],     g_twl[128*512];   // fwd DFT (padded 128 rows)
__device__ __align__(128) __nv_bfloat16 g_itwh[512*64],     g_itwl[512*64];   // inv DFT

// ---------------------------------------------------------------------------
// PTX helpers (arch-portable: ldmatrix / mma.sync / cp.async only)
// ---------------------------------------------------------------------------
__device__ __forceinline__ uint32_t smem_u32(const void* p) {
    uint32_t a;
    asm("{ .reg .u64 t; cvta.to.shared.u64 t, %1; cvt.u32.u64 %0, t; }" : "=r"(a) : "l"(p));
    return a;
}
#define CP16(d, s)  asm volatile("cp.async.cg.shared.global [%0], [%1], 16;" :: "r"(d), "l"(s) : "memory")
#define CP_COMMIT() asm volatile("cp.async.commit_group;" ::: "memory")
#define CP_WAIT0()  asm volatile("cp.async.wait_group 0;" ::: "memory")

#define LDSM4(r0, r1, r2, r3, a) \
    asm volatile("ldmatrix.sync.aligned.m8n8.x4.shared.b16 {%0,%1,%2,%3}, [%4];" \
        : "=r"(r0), "=r"(r1), "=r"(r2), "=r"(r3) : "r"(a))

#define MMA16816(c, a0, a1, a2, a3, b0, b1) \
    asm volatile("mma.sync.aligned.m16n8k16.row.col.f32.bf16.bf16.f32 " \
        "{%0,%1,%2,%3}, {%4,%5,%6,%7}, {%8,%9}, {%0,%1,%2,%3};" \
        : "+f"((c)[0]), "+f"((c)[1]), "+f"((c)[2]), "+f"((c)[3]) \
        : "r"(a0), "r"(a1), "r"(a2), "r"(a3), "r"(b0), "r"(b1))

__device__ __forceinline__ void split2(float v, __nv_bfloat16& h, __nv_bfloat16& l) {
    h = __float2bfloat16(v);
    l = __float2bfloat16(v - __bfloat162float(h));
}

// ---------------------------------------------------------------------------
// Tensor-core GEMM: C[m,n] = sum_k A[m,k]*B[n,k]  (+bias) (+Cin) (relu)
//   A, B pre-split bf16 hi/lo planes [.,K]. Split-3: AhBh + AlBh + AhBl.
//   Tile 128x128, BK=32, 256 threads, double-buffered cp.async, 2 CTAs/SM.
//   SMEM rows at 80B pitch -> conflict-free ldmatrix. K mult of 32.
// ---------------------------------------------------------------------------
#define MG_PL   (128 * 80)
#define MG_STG  (4 * MG_PL)          // 40960 B
#define MG_SMEM (2 * MG_STG)         // 81920 B
#define OAH 0
#define OAL (1 * MG_PL)
#define OBH (2 * MG_PL)
#define OBL (3 * MG_PL)

template <int RELU, int ADDC, int BIAS, int OUTPL>
__global__ void __launch_bounds__(256, 2)
mgemm_k(const __nv_bfloat16* __restrict__ Ah, const __nv_bfloat16* __restrict__ Al,
        const __nv_bfloat16* __restrict__ Bh, const __nv_bfloat16* __restrict__ Bl,
        const float* __restrict__ bias, const float* __restrict__ Cin,
        float* __restrict__ C, __nv_bfloat16* __restrict__ Oh,
        __nv_bfloat16* __restrict__ Ol, int K, int Nout) {
    extern __shared__ __align__(128) char smem[];
    const uint32_t sb = smem_u32(smem);
    const int tid = threadIdx.x, lane = tid & 31, wid = tid >> 5;
    const int wm = wid & 3, wn = wid >> 2;       // warps 4 x 2
    const int m0 = blockIdx.y * 128, n0 = blockIdx.x * 128;

    float acc[2][8][4];
#pragma unroll
    for (int i = 0; i < 2; i++)
#pragma unroll
        for (int j = 0; j < 8; j++)
#pragma unroll
            for (int t = 0; t < 4; t++) acc[i][j][t] = 0.f;

    const uint32_t a_off = (uint32_t)((wm * 32 + (lane & 7) + ((lane >> 3) & 1) * 8) * 80
                                      + (lane >> 4) * 16);
    const uint32_t b_off = (uint32_t)((wn * 64 + ((lane >> 4) & 1) * 8 + (lane & 7)) * 80
                                      + ((lane >> 3) & 1) * 16);

    // per-thread fixed source coordinates for cp.async (A: 512 sts of 16B, B same)
    const int cr = tid >> 1;                 // 0..127 row
    const int cch = tid & 1;                 // 16B-chunk pair selector
    auto cpAB = [&](int c, int s) {
        const uint32_t base = sb + s * MG_STG;
        const size_t ko = (size_t)c * 32 + cch * 16;
        const uint32_t doff = (uint32_t)(cr * 80 + cch * 32);
        const __nv_bfloat16* a0 = Ah + (size_t)(m0 + cr) * K + ko;
        const __nv_bfloat16* a1 = Al + (size_t)(m0 + cr) * K + ko;
        const __nv_bfloat16* b0 = Bh + (size_t)(n0 + cr) * K + ko;
        const __nv_bfloat16* b1 = Bl + (size_t)(n0 + cr) * K + ko;
        CP16(base + OAH + doff, a0);      CP16(base + OAH + doff + 16, a0 + 8);
        CP16(base + OAL + doff, a1);      CP16(base + OAL + doff + 16, a1 + 8);
        CP16(base + OBH + doff, b0);      CP16(base + OBH + doff + 16, b0 + 8);
        CP16(base + OBL + doff, b1);      CP16(base + OBL + doff + 16, b1 + 8);
        CP_COMMIT();
    };

    const int NC = K >> 5;
    cpAB(0, 0);
    for (int c = 0; c < NC; c++) {
        const int s = c & 1;
        CP_WAIT0();
        __syncthreads();
        if (c + 1 < NC) cpAB(c + 1, s ^ 1);      // overlaps compute below
        const uint32_t base = sb + s * MG_STG;
#pragma unroll
        for (int ks = 0; ks < 2; ks++) {
            const uint32_t koff = ks * 32;
            uint32_t ah[2][4], al[2][4];
#pragma unroll
            for (int mi = 0; mi < 2; mi++) {
                LDSM4(ah[mi][0], ah[mi][1], ah[mi][2], ah[mi][3],
                      base + OAH + a_off + mi * (16 * 80) + koff);
                LDSM4(al[mi][0], al[mi][1], al[mi][2], al[mi][3],
                      base + OAL + a_off + mi * (16 * 80) + koff);
            }
#pragma unroll
            for (int np = 0; np < 4; np++) {
                uint32_t bh[4], bl[4];
                LDSM4(bh[0], bh[1], bh[2], bh[3],
                      base + OBH + b_off + np * (16 * 80) + koff);
                LDSM4(bl[0], bl[1], bl[2], bl[3],
                      base + OBL + b_off + np * (16 * 80) + koff);
#pragma unroll
                for (int mi = 0; mi < 2; mi++) {
#pragma unroll
                    for (int t = 0; t < 2; t++) {
                        float* cc = acc[mi][np * 2 + t];
                        MMA16816(cc, ah[mi][0], ah[mi][1], ah[mi][2], ah[mi][3],
                                 bh[2*t], bh[2*t + 1]);
                        MMA16816(cc, al[mi][0], al[mi][1], al[mi][2], al[mi][3],
                                 bh[2*t], bh[2*t + 1]);
                        MMA16816(cc, ah[mi][0], ah[mi][1], ah[mi][2], ah[mi][3],
                                 bl[2*t], bl[2*t + 1]);
                    }
                }
            }
        }
    }

    // epilogue
#pragma unroll
    for (int mi = 0; mi < 2; mi++) {
        const int r0 = m0 + wm * 32 + mi * 16 + (lane >> 2);
#pragma unroll
        for (int ni = 0; ni < 8; ni++) {
            const int col = n0 + wn * 64 + ni * 8 + 2 * (lane & 3);
            if (col >= Nout) continue;
            float v00 = acc[mi][ni][0], v01 = acc[mi][ni][1];
            float v10 = acc[mi][ni][2], v11 = acc[mi][ni][3];
            if (BIAS) {
                float2 bv = *(const float2*)&bias[col];
                v00 += bv.x; v01 += bv.y; v10 += bv.x; v11 += bv.y;
            }
            const size_t o0 = (size_t)r0 * Nout + col;
            const size_t o1 = (size_t)(r0 + 8) * Nout + col;
            if (ADDC) {
                float2 c0 = *(const float2*)&Cin[o0];
                float2 c1 = *(const float2*)&Cin[o1];
                v00 += c0.x; v01 += c0.y; v10 += c1.x; v11 += c1.y;
            }
            if (RELU) {
                v00 = fmaxf(v00, 0.f); v01 = fmaxf(v01, 0.f);
                v10 = fmaxf(v10, 0.f); v11 = fmaxf(v11, 0.f);
            }
            if (OUTPL) {
                __nv_bfloat162 h0, l0, h1, l1;
                split2(v00, h0.x, l0.x); split2(v01, h0.y, l0.y);
                split2(v10, h1.x, l1.x); split2(v11, h1.y, l1.y);
                *(__nv_bfloat162*)&Oh[o0] = h0;
                *(__nv_bfloat162*)&Ol[o0] = l0;
                *(__nv_bfloat162*)&Oh[o1] = h1;
                *(__nv_bfloat162*)&Ol[o1] = l1;
            } else {
                *(float2*)&C[o0] = make_float2(v00, v01);
                *(float2*)&C[o1] = make_float2(v10, v11);
            }
        }
    }
}

template <int R, int AD, int BI, int OP>
static void mg2(const __nv_bfloat16* Ah, const __nv_bfloat16* Al,
                const __nv_bfloat16* Bh, const __nv_bfloat16* Bl,
                const float* bias, const float* Cin, float* C,
                __nv_bfloat16* Oh, __nv_bfloat16* Ol,
                int M, int Npad, int K, int Nout) {
    cudaFuncSetAttribute(mgemm_k<R, AD, BI, OP>,
                         cudaFuncAttributeMaxDynamicSharedMemorySize, MG_SMEM);
    dim3 g(Npad / 128, M / 128);
    mgemm_k<R, AD, BI, OP><<<g, 256, MG_SMEM>>>(Ah, Al, Bh, Bl, bias, Cin, C, Oh, Ol, K, Nout);
}

// ---------------------------------------------------------------------------
// Weight split + twiddle init
// ---------------------------------------------------------------------------
__global__ void split_k(const float* __restrict__ s, __nv_bfloat16* __restrict__ h,
                        __nv_bfloat16* __restrict__ l, int n) {
    int i = blockIdx.x * blockDim.x + threadIdx.x;
    if (i < n) split2(s[i], h[i], l[i]);
}

__global__ void init_tw_k(__nv_bfloat16* twh, __nv_bfloat16* twl,
                          __nv_bfloat16* itwh, __nv_bfloat16* itwl) {
    int i = blockIdx.x * blockDim.x + threadIdx.x;   // 0..65535
    {
        int c = i >> 9, l = i & 511;
        double v = 0.0;
        if (c < 32)       v = cos((TWOPI / 512.0) * (double)(l * c));
        else if (c < 64)  v = -sin((TWOPI / 512.0) * (double)(l * (c - 32)));
        split2((float)v, twh[i], twl[i]);
    }
    if (i < 512 * 64) {
        int l = i >> 6, c = i & 63;
        double v;
        if (c == 0)       v = 1.0 / 512.0;
        else if (c < 32)  v = 2.0 * cos((TWOPI / 512.0) * (double)(l * c)) / 512.0;
        else if (c == 32) v = 0.0;
        else              v = -2.0 * sin((TWOPI / 512.0) * (double)(l * (c - 32))) / 512.0;
        split2((float)v, itwh[i], itwl[i]);
    }
}

// ---------------------------------------------------------------------------
// Embedding (writes f32 + planes)
// ---------------------------------------------------------------------------
__global__ void embed_k(const int* __restrict__ x_app, const float* __restrict__ x_time,
                        const float* __restrict__ emb, const float* __restrict__ tw,
                        const float* __restrict__ tb, float* __restrict__ x,
                        __nv_bfloat16* __restrict__ ph, __nv_bfloat16* __restrict__ po) {
    int b = blockIdx.y, l = blockIdx.x, d = threadIdx.x;
    int a = x_app[b * LL + l];
    float t = x_time[b * LL + l];
    size_t idx = ((size_t)b * LL + l) * DDIM + d;
    float v = emb[(size_t)a * DDIM + d] + t * tw[d] + tb[d];
    x[idx] = v;
    split2(v, ph[idx], po[idx]);
}

// ---------------------------------------------------------------------------
// fp32 SIMT GEMM (final projection only: K=536)
// ---------------------------------------------------------------------------
__global__ __launch_bounds__(256, 2)
void gemm_nt_kernel(const float* __restrict__ A, const float* __restrict__ Bm,
                    const float* __restrict__ bias, float* __restrict__ Cout,
                    int M, int N, int K) {
    __shared__ float As[8][128];
    __shared__ float Bs[8][128];
    const int tid = threadIdx.x;
    const int m0 = blockIdx.y * 128, n0 = blockIdx.x * 128;
    const int lr = tid >> 1, lk = (tid & 1) * 4;
    const int tx = tid & 15, ty = tid >> 4;
    const int arow = m0 + lr, brow = n0 + lr;
    const bool aval = arow < M, bval = brow < N;
    const float* Ap = A + (size_t)arow * K + lk;
    const float* Bp = Bm + (size_t)brow * K + lk;
    float acc[8][8];
#pragma unroll
    for (int i = 0; i < 8; i++)
#pragma unroll
        for (int j = 0; j < 8; j++) acc[i][j] = 0.f;
    const float4 z4 = make_float4(0.f, 0.f, 0.f, 0.f);
    for (int k0 = 0; k0 < K; k0 += 8) {
        float4 a = z4, b = z4;
        if (aval && lk + k0 < K) a = *(const float4*)Ap;
        if (bval && lk + k0 < K) b = *(const float4*)Bp;
        Ap += 8; Bp += 8;
        __syncthreads();
        As[lk+0][lr]=a.x; As[lk+1][lr]=a.y; As[lk+2][lr]=a.z; As[lk+3][lr]=a.w;
        Bs[lk+0][lr]=b.x; Bs[lk+1][lr]=b.y; Bs[lk+2][lr]=b.z; Bs[lk+3][lr]=b.w;
        __syncthreads();
#pragma unroll
        for (int k = 0; k < 8; k++) {
            float arv[8], brv[8];
            *(float4*)&arv[0] = *(const float4*)&As[k][ty*8];
            *(float4*)&arv[4] = *(const float4*)&As[k][ty*8+4];
            *(float4*)&brv[0] = *(const float4*)&Bs[k][tx*8];
            *(float4*)&brv[4] = *(const float4*)&Bs[k][tx*8+4];
#pragma unroll
            for (int i = 0; i < 8; i++)
#pragma unroll
                for (int j = 0; j < 8; j++) acc[i][j] += arv[i] * brv[j];
        }
    }
#pragma unroll
    for (int i = 0; i < 8; i++) {
        int m = m0 + ty * 8 + i;
        if (m >= M) continue;
        size_t row = (size_t)m * N;
#pragma unroll
        for (int jg = 0; jg < 8; jg++) {
            int n = n0 + tx * 8 + jg;
            if (n >= N) continue;
            Cout[row + n] = acc[i][jg] + bias[n];
        }
    }
}

// ---------------------------------------------------------------------------
// Per-batch 512x512 transpose: f32 in -> bf16 hi/lo planes out (transposed)
// ---------------------------------------------------------------------------
__global__ void transpose_split_k(const float* __restrict__ in,
                                  __nv_bfloat16* __restrict__ ph,
                                  __nv_bfloat16* __restrict__ po) {
    __shared__ float tile[32][33];
    int b = blockIdx.z;
    const float* ip = in + (size_t)b * (512 * 512);
    int i0 = blockIdx.y * 32, j0 = blockIdx.x * 32;
#pragma unroll
    for (int r = 0; r < 32; r += 8)
        tile[threadIdx.y + r][threadIdx.x] =
            ip[(size_t)(i0 + threadIdx.y + r) * 512 + j0 + threadIdx.x];
    __syncthreads();
#pragma unroll
    for (int r = 0; r < 32; r += 8) {
        float v = tile[threadIdx.x][threadIdx.y + r];
        size_t o = (size_t)b * (512 * 512) + (size_t)(j0 + threadIdx.y + r) * 512
                   + i0 + threadIdx.x;
        split2(v, ph[o], po[o]);
    }
}

// ---------------------------------------------------------------------------
// Complex mode mixing -> writes bf16 hi/lo planes [M][64]
// ---------------------------------------------------------------------------
__global__ void modemix_k(const float* __restrict__ xs, const float* __restrict__ wr,
                          const float* __restrict__ wi, __nv_bfloat16* __restrict__ ph,
                          __nv_bfloat16* __restrict__ po) {
    int mode = blockIdx.x, h = blockIdx.y;
    __shared__ float Xr[64][32], Xi[64][32], Wr[32][64], Wi[32][64];
    int tid = threadIdx.x;
    int tb = tid >> 4, to = tid & 15;
    float cr[4][4], ci[4][4];
#pragma unroll
    for (int a = 0; a < 4; a++)
#pragma unroll
        for (int c = 0; c < 4; c++) { cr[a][c] = 0.f; ci[a][c] = 0.f; }
    for (int i0 = 0; i0 < 64; i0 += 32) {
#pragma unroll
        for (int j = 0; j < 8; j++) {
            int e = tid * 8 + j;
            int b = e >> 5, ii = e & 31;
            size_t xrow = ((size_t)b * 512 + h * 64 + i0 + ii) * 64;
            Xr[b][ii] = xs[xrow + mode];
            Xi[b][ii] = xs[xrow + 32 + mode];
            int wi2 = e >> 6, o = e & 63;
            size_t widx = (((size_t)h * 64 + i0 + wi2) * 64 + o) * 32 + mode;
            Wr[wi2][o] = wr[widx];
            Wi[wi2][o] = wi[widx];
        }
        __syncthreads();
#pragma unroll 8
        for (int ii = 0; ii < 32; ii++) {
            float xr[4], xi4[4], wrv[4], wiv[4];
#pragma unroll
            for (int a = 0; a < 4; a++) { xr[a] = Xr[tb*4+a][ii]; xi4[a] = Xi[tb*4+a][ii]; }
#pragma unroll
            for (int c = 0; c < 4; c++) { wrv[c] = Wr[ii][to*4+c]; wiv[c] = Wi[ii][to*4+c]; }
#pragma unroll
            for (int a = 0; a < 4; a++)
#pragma unroll
                for (int c = 0; c < 4; c++) {
                    cr[a][c] += xr[a] * wrv[c] - xi4[a] * wiv[c];
                    ci[a][c] += xr[a] * wiv[c] + xi4[a] * wrv[c];
                }
        }
        __syncthreads();
    }
#pragma unroll
    for (int a = 0; a < 4; a++) {
        int b = tb * 4 + a;
#pragma unroll
        for (int c = 0; c < 4; c++) {
            int o = to * 4 + c;
            size_t base = ((size_t)b * 512 + h * 64 + o) * 64;
            split2(cr[a][c], ph[base + mode], po[base + mode]);
            split2(ci[a][c], ph[base + 32 + mode], po[base + 32 + mode]);
        }
    }
}

// ---------------------------------------------------------------------------
// Series decomposition: out = in - moving_avg_25(in); writes f32 + planes
// ---------------------------------------------------------------------------
__global__ void decomp_split_k(const float* __restrict__ in, float* __restrict__ out,
                               __nv_bfloat16* __restrict__ ph, __nv_bfloat16* __restrict__ po) {
    int b = blockIdx.y, l = blockIdx.x, d = threadIdx.x;
    const float* base = in + (size_t)b * (LL * DDIM);
    float s = 0.f;
#pragma unroll
    for (int j = -12; j <= 12; j++) {
        int ll = l + j;
        ll = ll < 0 ? 0 : (ll > 511 ? 511 : ll);
        s += base[(size_t)ll * DDIM + d];
    }
    size_t idx = ((size_t)b * LL + l) * DDIM + d;
    float v = base[(size_t)l * DDIM + d] - s * (1.0f / 25.0f);
    out[idx] = v;
    split2(v, ph[idx], po[idx]);
}

// ---------------------------------------------------------------------------
// LayerNorm + last-token concat
// ---------------------------------------------------------------------------
__device__ __forceinline__ float blocksum512(float v, float* red) {
    int lane = threadIdx.x & 31, w = threadIdx.x >> 5;
#pragma unroll
    for (int o = 16; o; o >>= 1) v += __shfl_down_sync(0xffffffffu, v, o);
    if (lane == 0) red[w] = v;
    __syncthreads();
    if (w == 0) {
        float t = (lane < 16) ? red[lane] : 0.f;
#pragma unroll
        for (int o = 8; o; o >>= 1) t += __shfl_down_sync(0xffffffffu, t, o);
        if (lane == 0) red[0] = t;
    }
    __syncthreads();
    float r = red[0];
    __syncthreads();
    return r;
}

__global__ void layernorm_k(const float* __restrict__ x, const float* __restrict__ w,
                            const float* __restrict__ bb, float* __restrict__ xh) {
    __shared__ float red[32];
    int b = blockIdx.y, l = blockIdx.x, d = threadIdx.x;
    size_t base = ((size_t)b * LL + l) * DDIM;
    float v = x[base + d];
    float mu = blocksum512(v, red) * (1.f / 512.f);
    float dv = v - mu;
    float var = blocksum512(dv * dv, red) * (1.f / 512.f);
    xh[base + d] = dv * rsqrtf(var + 1e-5f) * w[d] + bb[d];
}

__global__ void lastcat_k(const float* __restrict__ xh, const float* __restrict__ time_vecs,
                          float* __restrict__ cat) {
    int b = blockIdx.x, d = threadIdx.x;
    float s = 0.f;
    for (int l = 0; l < LL; l++) s += xh[((size_t)b * LL + l) * DDIM + d];
    cat[b * KCAT + d] = xh[((size_t)b * LL + 511) * DDIM + d] - s * (1.f / 512.f);
    if (d < 24) cat[b * KCAT + 512 + d] = time_vecs[((size_t)b * LL + 511) * 24 + d];
}

// ---------------------------------------------------------------------------
// Host orchestration
// ---------------------------------------------------------------------------
extern "C" void kernel_launch(void* const* d_in, const int* in_sizes, int n_in,
                              void* d_out, int out_size) {
    (void)in_sizes; (void)n_in; (void)out_size;
    const int*   x_app     = (const int*)  d_in[0];
    const float* x_time    = (const float*)d_in[1];
    const float* time_vecs = (const float*)d_in[2];
    const float* emb       = (const float*)d_in[4];
    const float* time_w    = (const float*)d_in[5];
    const float* time_b    = (const float*)d_in[6];
    const float* Wq        = (const float*)d_in[7];
    const float* bq        = (const float*)d_in[8];
    const float* Wo        = (const float*)d_in[9];
    const float* bo        = (const float*)d_in[10];
    const float* four_wr   = (const float*)d_in[11];
    const float* four_wi   = (const float*)d_in[12];
    const float* conv1     = (const float*)d_in[13];
    const float* conv2     = (const float*)d_in[14];
    const float* norm_w    = (const float*)d_in[15];
    const float* norm_b    = (const float*)d_in[16];
    const float* proj_w    = (const float*)d_in[17];
    const float* proj_b    = (const float*)d_in[18];

    float *gx, *gq, *gt2, *gcat;
    __nv_bfloat16 *pah, *pal, *yph, *ypl;
    __nv_bfloat16 *wqh, *wql, *woh, *wol, *c1h, *c1l, *c2h, *c2l, *twh, *twl, *itwh, *itwl;
    cudaGetSymbolAddress((void**)&gx,   g_x);
    cudaGetSymbolAddress((void**)&gq,   g_q);
    cudaGetSymbolAddress((void**)&gt2,  g_t2);
    cudaGetSymbolAddress((void**)&gcat, g_cat);
    cudaGetSymbolAddress((void**)&pah,  g_pah);  cudaGetSymbolAddress((void**)&pal, g_pal);
    cudaGetSymbolAddress((void**)&yph,  g_yph);  cudaGetSymbolAddress((void**)&ypl, g_ypl);
    cudaGetSymbolAddress((void**)&wqh,  g_wqh);  cudaGetSymbolAddress((void**)&wql, g_wql);
    cudaGetSymbolAddress((void**)&woh,  g_woh);  cudaGetSymbolAddress((void**)&wol, g_wol);
    cudaGetSymbolAddress((void**)&c1h,  g_c1h);  cudaGetSymbolAddress((void**)&c1l, g_c1l);
    cudaGetSymbolAddress((void**)&c2h,  g_c2h);  cudaGetSymbolAddress((void**)&c2l, g_c2l);
    cudaGetSymbolAddress((void**)&twh,  g_twh);  cudaGetSymbolAddress((void**)&twl, g_twl);
    cudaGetSymbolAddress((void**)&itwh, g_itwh); cudaGetSymbolAddress((void**)&itwl, g_itwl);

    const int M = MTOT;   // 32768

    init_tw_k<<<256, 256>>>(twh, twl, itwh, itwl);
    split_k<<<(2*DDIM*DDIM + 255)/256, 256>>>(Wq, wqh, wql, 2*DDIM*DDIM);
    split_k<<<(2*DDIM*DDIM + 255)/256, 256>>>(Wo, woh, wol, 2*DDIM*DDIM);
    split_k<<<(2*DFF*DDIM + 255)/256, 256>>>(conv1, c1h, c1l, 2*DFF*DDIM);
    split_k<<<(2*DDIM*DFF + 255)/256, 256>>>(conv2, c2h, c2l, 2*DDIM*DFF);

    embed_k<<<dim3(LL, BB), DDIM>>>(x_app, x_time, emb, time_w, time_b, gx, pah, pal);

    dim3 tgrid(16, 16, BB), tblk(32, 8);
    for (int l = 0; l < 2; l++) {
        const float* bql = bq + (size_t)l * DDIM;
        const float* bol = bo + (size_t)l * DDIM;
        const float* wrl = four_wr + (size_t)l * HH * EE * EE * NMODES;
        const float* wil = four_wi + (size_t)l * HH * EE * EE * NMODES;
        size_t owq = (size_t)l * DDIM * DDIM;
        size_t oc1 = (size_t)l * DFF * DDIM;
        size_t oc2 = (size_t)l * DDIM * DFF;

        // q = x @ Wq^T + bq  (f32 out)
        mg2<0,0,1,0>(pah, pal, wqh + owq, wql + owq, bql, nullptr, gq,
                     nullptr, nullptr, M, 512, 512, 512);
        // qT planes
        transpose_split_k<<<tgrid, tblk>>>(gq, pah, pal);
        // forward DFT: xs = qT @ TW^T  (Nout=64, f32)
        mg2<0,0,0,0>(pah, pal, twh, twl, nullptr, nullptr, gt2,
                     nullptr, nullptr, M, 128, 512, 64);
        // complex mode mixing -> g planes [M][64]
        modemix_k<<<dim3(NMODES, HH), 256>>>(gt2, wrl, wil, pah, pal);
        // inverse DFT: foutT = g @ ITW^T (f32)
        mg2<0,0,0,0>(pah, pal, itwh, itwl, nullptr, nullptr, gq,
                     nullptr, nullptr, M, 512, 64, 512);
        // fout planes
        transpose_split_k<<<tgrid, tblk>>>(gq, pah, pal);
        // tmp = fout @ Wo^T + bo + x  (f32)
        mg2<0,1,1,0>(pah, pal, woh + owq, wol + owq, bol, gx, gt2,
                     nullptr, nullptr, M, 512, 512, 512);
        // x = tmp - movavg(tmp)  (f32 + planes)
        decomp_split_k<<<dim3(LL, BB), DDIM>>>(gt2, gx, pah, pal);
        // y = relu(x @ c1^T)  (planes out only)
        mg2<1,0,0,1>(pah, pal, c1h + oc1, c1l + oc1, nullptr, nullptr, nullptr,
                     yph, ypl, M, 2048, 512, 2048);
        // tmp = y @ c2^T + x  (f32)
        mg2<0,1,0,0>(yph, ypl, c2h + oc2, c2l + oc2, nullptr, gx, gt2,
                     nullptr, nullptr, M, 512, 2048, 512);
        // x = tmp - movavg(tmp)
        decomp_split_k<<<dim3(LL, BB), DDIM>>>(gt2, gx, pah, pal);
    }

    layernorm_k<<<dim3(LL, BB), DDIM>>>(gx, norm_w, norm_b, gq);
    lastcat_k<<<BB, DDIM>>>(gq, time_vecs, gcat);
    gemm_nt_kernel<<<dim3((NAPP + 127) / 128, 1), 256>>>(gcat, proj_w, proj_b,
                                                         (float*)d_out, BB, NAPP, KCAT);
}

// round 6
// speedup vs baseline: 2.1643x; 2.0475x over previous
#include <cuda_runtime.h>
#include <cuda_fp16.h>
#include <math.h>
#include <stdint.h>

// Problem constants
#define BB    64
#define LL    512
#define DDIM  512
#define HH    8
#define EE    64
#define DFF   2048
#define NMODES 32
#define NAPP  10000
#define KCAT  536    // D + 24
#define MTOT  (BB*LL)
#define TWOPI 6.283185307179586476925286766559

// ---------------------------------------------------------------------------
// Scratch (device globals — no runtime allocation allowed)
// ---------------------------------------------------------------------------
__device__ __align__(128) float g_x [MTOT*DDIM];
__device__ __align__(128) float g_q [MTOT*DDIM];
__device__ __align__(128) float g_t2[MTOT*DDIM];
__device__ __align__(128) float g_cat[BB*KCAT];
__device__ __align__(128) float g_acc[BB*DDIM];

// fp16 activation / weight planes
__device__ __align__(128) __half g_pa [MTOT*DDIM];
__device__ __align__(128) __half g_yp [MTOT*DFF];
__device__ __align__(128) __half g_wq [2*DDIM*DDIM];
__device__ __align__(128) __half g_wo [2*DDIM*DDIM];
__device__ __align__(128) __half g_c1 [2*DFF*DDIM];
__device__ __align__(128) __half g_c2 [2*DDIM*DFF];
__device__ __align__(128) __half g_tw [128*512];      // fwd DFT (padded 128 rows)
__device__ __align__(128) __half g_itw[512*64];       // inv DFT

// ---------------------------------------------------------------------------
// PTX helpers (arch-portable: ldmatrix / mma.sync / cp.async only)
// ---------------------------------------------------------------------------
__device__ __forceinline__ uint32_t smem_u32(const void* p) {
    uint32_t a;
    asm("{ .reg .u64 t; cvta.to.shared.u64 t, %1; cvt.u32.u64 %0, t; }" : "=r"(a) : "l"(p));
    return a;
}
#define CP16(d, s)  asm volatile("cp.async.cg.shared.global [%0], [%1], 16;" :: "r"(d), "l"(s) : "memory")
#define CP_COMMIT() asm volatile("cp.async.commit_group;" ::: "memory")
#define CP_WAIT0()  asm volatile("cp.async.wait_group 0;" ::: "memory")

#define LDSM4(r0, r1, r2, r3, a) \
    asm volatile("ldmatrix.sync.aligned.m8n8.x4.shared.b16 {%0,%1,%2,%3}, [%4];" \
        : "=r"(r0), "=r"(r1), "=r"(r2), "=r"(r3) : "r"(a))

#define MMAF16(c, a0, a1, a2, a3, b0, b1) \
    asm volatile("mma.sync.aligned.m16n8k16.row.col.f32.f16.f16.f32 " \
        "{%0,%1,%2,%3}, {%4,%5,%6,%7}, {%8,%9}, {%0,%1,%2,%3};" \
        : "+f"((c)[0]), "+f"((c)[1]), "+f"((c)[2]), "+f"((c)[3]) \
        : "r"(a0), "r"(a1), "r"(a2), "r"(a3), "r"(b0), "r"(b1))

// ---------------------------------------------------------------------------
// Tensor-core GEMM (fp16 x fp16 -> fp32): C[m,n] = sum_k A[m,k]*B[n,k]
//   Tile 128x128, BK=32, 256 threads, double-buffered cp.async, 2 CTAs/SM.
//   80B row pitch -> conflict-free ldmatrix. K mult of 32.
// ---------------------------------------------------------------------------
#define MG_PL   (128 * 80)
#define MG_STG  (2 * MG_PL)          // 20480 B (A + B)
#define MG_SMEM (2 * MG_STG)         // 40960 B
#define OA 0
#define OB MG_PL

template <int RELU, int ADDC, int BIAS, int OUTPL>
__global__ void __launch_bounds__(256, 2)
mgemm_k(const __half* __restrict__ A, const __half* __restrict__ B,
        const float* __restrict__ bias, const float* __restrict__ Cin,
        float* __restrict__ C, __half* __restrict__ Oh, int K, int Nout) {
    extern __shared__ __align__(128) char smem[];
    const uint32_t sb = smem_u32(smem);
    const int tid = threadIdx.x, lane = tid & 31, wid = tid >> 5;
    const int wm = wid & 3, wn = wid >> 2;       // warps 4 x 2
    const int m0 = blockIdx.y * 128, n0 = blockIdx.x * 128;

    float acc[2][8][4];
#pragma unroll
    for (int i = 0; i < 2; i++)
#pragma unroll
        for (int j = 0; j < 8; j++)
#pragma unroll
            for (int t = 0; t < 4; t++) acc[i][j][t] = 0.f;

    const uint32_t a_off = (uint32_t)((wm * 32 + (lane & 7) + ((lane >> 3) & 1) * 8) * 80
                                      + (lane >> 4) * 16);
    const uint32_t b_off = (uint32_t)((wn * 64 + ((lane >> 4) & 1) * 8 + (lane & 7)) * 80
                                      + ((lane >> 3) & 1) * 16);

    const int cr = tid >> 1;                 // 0..127 row
    const int cch = tid & 1;                 // 16B-chunk pair selector
    auto cpAB = [&](int c, int s) {
        const uint32_t base = sb + s * MG_STG;
        const size_t ko = (size_t)c * 32 + cch * 16;
        const uint32_t doff = (uint32_t)(cr * 80 + cch * 32);
        const __half* a0 = A + (size_t)(m0 + cr) * K + ko;
        const __half* b0 = B + (size_t)(n0 + cr) * K + ko;
        CP16(base + OA + doff, a0);   CP16(base + OA + doff + 16, a0 + 8);
        CP16(base + OB + doff, b0);   CP16(base + OB + doff + 16, b0 + 8);
        CP_COMMIT();
    };

    const int NC = K >> 5;
    cpAB(0, 0);
    for (int c = 0; c < NC; c++) {
        const int s = c & 1;
        CP_WAIT0();
        __syncthreads();
        if (c + 1 < NC) cpAB(c + 1, s ^ 1);      // overlaps compute below
        const uint32_t base = sb + s * MG_STG;
#pragma unroll
        for (int ks = 0; ks < 2; ks++) {
            const uint32_t koff = ks * 32;
            uint32_t a[2][4];
#pragma unroll
            for (int mi = 0; mi < 2; mi++)
                LDSM4(a[mi][0], a[mi][1], a[mi][2], a[mi][3],
                      base + OA + a_off + mi * (16 * 80) + koff);
#pragma unroll
            for (int np = 0; np < 4; np++) {
                uint32_t b[4];
                LDSM4(b[0], b[1], b[2], b[3],
                      base + OB + b_off + np * (16 * 80) + koff);
#pragma unroll
                for (int mi = 0; mi < 2; mi++) {
#pragma unroll
                    for (int t = 0; t < 2; t++) {
                        MMAF16(acc[mi][np * 2 + t], a[mi][0], a[mi][1], a[mi][2], a[mi][3],
                               b[2*t], b[2*t + 1]);
                    }
                }
            }
        }
    }

    // epilogue
#pragma unroll
    for (int mi = 0; mi < 2; mi++) {
        const int r0 = m0 + wm * 32 + mi * 16 + (lane >> 2);
#pragma unroll
        for (int ni = 0; ni < 8; ni++) {
            const int col = n0 + wn * 64 + ni * 8 + 2 * (lane & 3);
            if (col >= Nout) continue;
            float v00 = acc[mi][ni][0], v01 = acc[mi][ni][1];
            float v10 = acc[mi][ni][2], v11 = acc[mi][ni][3];
            if (BIAS) {
                float2 bv = *(const float2*)&bias[col];
                v00 += bv.x; v01 += bv.y; v10 += bv.x; v11 += bv.y;
            }
            const size_t o0 = (size_t)r0 * Nout + col;
            const size_t o1 = (size_t)(r0 + 8) * Nout + col;
            if (ADDC) {
                float2 c0 = *(const float2*)&Cin[o0];
                float2 c1 = *(const float2*)&Cin[o1];
                v00 += c0.x; v01 += c0.y; v10 += c1.x; v11 += c1.y;
            }
            if (RELU) {
                v00 = fmaxf(v00, 0.f); v01 = fmaxf(v01, 0.f);
                v10 = fmaxf(v10, 0.f); v11 = fmaxf(v11, 0.f);
            }
            if (OUTPL) {
                __half2 h0, h1;
                h0.x = __float2half_rn(v00); h0.y = __float2half_rn(v01);
                h1.x = __float2half_rn(v10); h1.y = __float2half_rn(v11);
                *(__half2*)&Oh[o0] = h0;
                *(__half2*)&Oh[o1] = h1;
            } else {
                *(float2*)&C[o0] = make_float2(v00, v01);
                *(float2*)&C[o1] = make_float2(v10, v11);
            }
        }
    }
}

template <int R, int AD, int BI, int OP>
static void mg2(const __half* A, const __half* B, const float* bias,
                const float* Cin, float* C, __half* Oh,
                int M, int Npad, int K, int Nout) {
    cudaFuncSetAttribute(mgemm_k<R, AD, BI, OP>,
                         cudaFuncAttributeMaxDynamicSharedMemorySize, MG_SMEM);
    dim3 g(Npad / 128, M / 128);
    mgemm_k<R, AD, BI, OP><<<g, 256, MG_SMEM>>>(A, B, bias, Cin, C, Oh, K, Nout);
}

// ---------------------------------------------------------------------------
// Weight conversion + twiddle init
// ---------------------------------------------------------------------------
__global__ void cvt_k(const float* __restrict__ s, __half* __restrict__ h, int n) {
    int i = blockIdx.x * blockDim.x + threadIdx.x;
    if (i < n) h[i] = __float2half_rn(s[i]);
}

__global__ void init_tw_k(__half* tw, __half* itw) {
    int i = blockIdx.x * blockDim.x + threadIdx.x;   // 0..65535
    {
        int c = i >> 9, l = i & 511;
        double v = 0.0;
        if (c < 32)       v = cos((TWOPI / 512.0) * (double)(l * c));
        else if (c < 64)  v = -sin((TWOPI / 512.0) * (double)(l * (c - 32)));
        tw[i] = __float2half_rn((float)v);
    }
    if (i < 512 * 64) {
        int l = i >> 6, c = i & 63;
        double v;
        if (c == 0)       v = 1.0 / 512.0;
        else if (c < 32)  v = 2.0 * cos((TWOPI / 512.0) * (double)(l * c)) / 512.0;
        else if (c == 32) v = 0.0;
        else              v = -2.0 * sin((TWOPI / 512.0) * (double)(l * (c - 32))) / 512.0;
        itw[i] = __float2half_rn((float)v);
    }
}

// ---------------------------------------------------------------------------
// Embedding (writes f32 + fp16 plane)
// ---------------------------------------------------------------------------
__global__ void embed_k(const int* __restrict__ x_app, const float* __restrict__ x_time,
                        const float* __restrict__ emb, const float* __restrict__ tw,
                        const float* __restrict__ tb, float* __restrict__ x,
                        __half* __restrict__ pa) {
    int b = blockIdx.y, l = blockIdx.x, d = threadIdx.x;
    int a = x_app[b * LL + l];
    float t = x_time[b * LL + l];
    size_t idx = ((size_t)b * LL + l) * DDIM + d;
    float v = emb[(size_t)a * DDIM + d] + t * tw[d] + tb[d];
    x[idx] = v;
    pa[idx] = __float2half_rn(v);
}

// ---------------------------------------------------------------------------
// fp32 SIMT GEMM (final projection only: K=536)
// ---------------------------------------------------------------------------
__global__ __launch_bounds__(256, 2)
void gemm_nt_kernel(const float* __restrict__ A, const float* __restrict__ Bm,
                    const float* __restrict__ bias, float* __restrict__ Cout,
                    int M, int N, int K) {
    __shared__ float As[8][128];
    __shared__ float Bs[8][128];
    const int tid = threadIdx.x;
    const int m0 = blockIdx.y * 128, n0 = blockIdx.x * 128;
    const int lr = tid >> 1, lk = (tid & 1) * 4;
    const int tx = tid & 15, ty = tid >> 4;
    const int arow = m0 + lr, brow = n0 + lr;
    const bool aval = arow < M, bval = brow < N;
    const float* Ap = A + (size_t)arow * K + lk;
    const float* Bp = Bm + (size_t)brow * K + lk;
    float acc[8][8];
#pragma unroll
    for (int i = 0; i < 8; i++)
#pragma unroll
        for (int j = 0; j < 8; j++) acc[i][j] = 0.f;
    const float4 z4 = make_float4(0.f, 0.f, 0.f, 0.f);
    for (int k0 = 0; k0 < K; k0 += 8) {
        float4 a = z4, b = z4;
        if (aval && lk + k0 < K) a = *(const float4*)Ap;
        if (bval && lk + k0 < K) b = *(const float4*)Bp;
        Ap += 8; Bp += 8;
        __syncthreads();
        As[lk+0][lr]=a.x; As[lk+1][lr]=a.y; As[lk+2][lr]=a.z; As[lk+3][lr]=a.w;
        Bs[lk+0][lr]=b.x; Bs[lk+1][lr]=b.y; Bs[lk+2][lr]=b.z; Bs[lk+3][lr]=b.w;
        __syncthreads();
#pragma unroll
        for (int k = 0; k < 8; k++) {
            float arv[8], brv[8];
            *(float4*)&arv[0] = *(const float4*)&As[k][ty*8];
            *(float4*)&arv[4] = *(const float4*)&As[k][ty*8+4];
            *(float4*)&brv[0] = *(const float4*)&Bs[k][tx*8];
            *(float4*)&brv[4] = *(const float4*)&Bs[k][tx*8+4];
#pragma unroll
            for (int i = 0; i < 8; i++)
#pragma unroll
                for (int j = 0; j < 8; j++) acc[i][j] += arv[i] * brv[j];
        }
    }
#pragma unroll
    for (int i = 0; i < 8; i++) {
        int m = m0 + ty * 8 + i;
        if (m >= M) continue;
        size_t row = (size_t)m * N;
#pragma unroll
        for (int jg = 0; jg < 8; jg++) {
            int n = n0 + tx * 8 + jg;
            if (n >= N) continue;
            Cout[row + n] = acc[i][jg] + bias[n];
        }
    }
}

// ---------------------------------------------------------------------------
// Per-batch 512x512 transpose: f32 in -> fp16 plane out (transposed)
// ---------------------------------------------------------------------------
__global__ void transpose_split_k(const float* __restrict__ in, __half* __restrict__ pa) {
    __shared__ float tile[32][33];
    int b = blockIdx.z;
    const float* ip = in + (size_t)b * (512 * 512);
    int i0 = blockIdx.y * 32, j0 = blockIdx.x * 32;
#pragma unroll
    for (int r = 0; r < 32; r += 8)
        tile[threadIdx.y + r][threadIdx.x] =
            ip[(size_t)(i0 + threadIdx.y + r) * 512 + j0 + threadIdx.x];
    __syncthreads();
#pragma unroll
    for (int r = 0; r < 32; r += 8) {
        float v = tile[threadIdx.x][threadIdx.y + r];
        size_t o = (size_t)b * (512 * 512) + (size_t)(j0 + threadIdx.y + r) * 512
                   + i0 + threadIdx.x;
        pa[o] = __float2half_rn(v);
    }
}

// ---------------------------------------------------------------------------
// Complex mode mixing -> writes fp16 plane [M][64]
// ---------------------------------------------------------------------------
__global__ void modemix_k(const float* __restrict__ xs, const float* __restrict__ wr,
                          const float* __restrict__ wi, __half* __restrict__ pa) {
    int mode = blockIdx.x, h = blockIdx.y;
    __shared__ float Xr[64][32], Xi[64][32], Wr[32][64], Wi[32][64];
    int tid = threadIdx.x;
    int tb = tid >> 4, to = tid & 15;
    float cr[4][4], ci[4][4];
#pragma unroll
    for (int a = 0; a < 4; a++)
#pragma unroll
        for (int c = 0; c < 4; c++) { cr[a][c] = 0.f; ci[a][c] = 0.f; }
    for (int i0 = 0; i0 < 64; i0 += 32) {
#pragma unroll
        for (int j = 0; j < 8; j++) {
            int e = tid * 8 + j;
            int b = e >> 5, ii = e & 31;
            size_t xrow = ((size_t)b * 512 + h * 64 + i0 + ii) * 64;
            Xr[b][ii] = xs[xrow + mode];
            Xi[b][ii] = xs[xrow + 32 + mode];
            int wi2 = e >> 6, o = e & 63;
            size_t widx = (((size_t)h * 64 + i0 + wi2) * 64 + o) * 32 + mode;
            Wr[wi2][o] = wr[widx];
            Wi[wi2][o] = wi[widx];
        }
        __syncthreads();
#pragma unroll 8
        for (int ii = 0; ii < 32; ii++) {
            float xr[4], xi4[4], wrv[4], wiv[4];
#pragma unroll
            for (int a = 0; a < 4; a++) { xr[a] = Xr[tb*4+a][ii]; xi4[a] = Xi[tb*4+a][ii]; }
#pragma unroll
            for (int c = 0; c < 4; c++) { wrv[c] = Wr[ii][to*4+c]; wiv[c] = Wi[ii][to*4+c]; }
#pragma unroll
            for (int a = 0; a < 4; a++)
#pragma unroll
                for (int c = 0; c < 4; c++) {
                    cr[a][c] += xr[a] * wrv[c] - xi4[a] * wiv[c];
                    ci[a][c] += xr[a] * wiv[c] + xi4[a] * wrv[c];
                }
        }
        __syncthreads();
    }
#pragma unroll
    for (int a = 0; a < 4; a++) {
        int b = tb * 4 + a;
#pragma unroll
        for (int c = 0; c < 4; c++) {
            int o = to * 4 + c;
            size_t base = ((size_t)b * 512 + h * 64 + o) * 64;
            pa[base + mode] = __float2half_rn(cr[a][c]);
            pa[base + 32 + mode] = __float2half_rn(ci[a][c]);
        }
    }
}

// ---------------------------------------------------------------------------
// Series decomposition: rolling 25-window; writes f32 + fp16 plane
//   grid (4 dtiles, 8 ltiles, BB), block 128
// ---------------------------------------------------------------------------
__global__ void decomp_split_k(const float* __restrict__ in, float* __restrict__ out,
                               __half* __restrict__ pa) {
    int b = blockIdx.z;
    int d = blockIdx.x * 128 + threadIdx.x;
    int l0 = blockIdx.y * 64;
    const float* p = in + (size_t)b * (LL * DDIM) + d;
    float sum = 0.f;
#pragma unroll
    for (int j = -12; j <= 12; j++) {
        int t = l0 + j;
        t = t < 0 ? 0 : (t > 511 ? 511 : t);
        sum += p[(size_t)t * DDIM];
    }
    size_t obase = (size_t)b * (LL * DDIM) + d;
    for (int l = l0; l < l0 + 64; l++) {
        float v = p[(size_t)l * DDIM] - sum * (1.0f / 25.0f);
        out[obase + (size_t)l * DDIM] = v;
        pa[obase + (size_t)l * DDIM] = __float2half_rn(v);
        int jn = l + 13 > 511 ? 511 : l + 13;
        int jo = l - 12 < 0 ? 0 : l - 12;
        sum += p[(size_t)jn * DDIM] - p[(size_t)jo * DDIM];
    }
}

// ---------------------------------------------------------------------------
// LayerNorm + parallel last-token concat
// ---------------------------------------------------------------------------
__device__ __forceinline__ float blocksum512(float v, float* red) {
    int lane = threadIdx.x & 31, w = threadIdx.x >> 5;
#pragma unroll
    for (int o = 16; o; o >>= 1) v += __shfl_down_sync(0xffffffffu, v, o);
    if (lane == 0) red[w] = v;
    __syncthreads();
    if (w == 0) {
        float t = (lane < 16) ? red[lane] : 0.f;
#pragma unroll
        for (int o = 8; o; o >>= 1) t += __shfl_down_sync(0xffffffffu, t, o);
        if (lane == 0) red[0] = t;
    }
    __syncthreads();
    float r = red[0];
    __syncthreads();
    return r;
}

__global__ void layernorm_k(const float* __restrict__ x, const float* __restrict__ w,
                            const float* __restrict__ bb, float* __restrict__ xh) {
    __shared__ float red[32];
    int b = blockIdx.y, l = blockIdx.x, d = threadIdx.x;
    size_t base = ((size_t)b * LL + l) * DDIM;
    float v = x[base + d];
    float mu = blocksum512(v, red) * (1.f / 512.f);
    float dv = v - mu;
    float var = blocksum512(dv * dv, red) * (1.f / 512.f);
    xh[base + d] = dv * rsqrtf(var + 1e-5f) * w[d] + bb[d];
}

__global__ void zero_acc_k(float* __restrict__ acc) {
    acc[blockIdx.x * 512 + threadIdx.x] = 0.f;
}

__global__ void partial_sum_k(const float* __restrict__ xh, float* __restrict__ acc) {
    int b = blockIdx.y, d = threadIdx.x;
    int l0 = blockIdx.x * 64;
    float s = 0.f;
    for (int l = l0; l < l0 + 64; l++) s += xh[((size_t)b * LL + l) * DDIM + d];
    atomicAdd(&acc[b * DDIM + d], s);
}

__global__ void lastcat_k(const float* __restrict__ xh, const float* __restrict__ acc,
                          const float* __restrict__ time_vecs, float* __restrict__ cat) {
    int b = blockIdx.x, d = threadIdx.x;
    cat[b * KCAT + d] = xh[((size_t)b * LL + 511) * DDIM + d] - acc[b * DDIM + d] * (1.f / 512.f);
    if (d < 24) cat[b * KCAT + 512 + d] = time_vecs[((size_t)b * LL + 511) * 24 + d];
}

// ---------------------------------------------------------------------------
// Host orchestration
// ---------------------------------------------------------------------------
extern "C" void kernel_launch(void* const* d_in, const int* in_sizes, int n_in,
                              void* d_out, int out_size) {
    (void)in_sizes; (void)n_in; (void)out_size;
    const int*   x_app     = (const int*)  d_in[0];
    const float* x_time    = (const float*)d_in[1];
    const float* time_vecs = (const float*)d_in[2];
    const float* emb       = (const float*)d_in[4];
    const float* time_w    = (const float*)d_in[5];
    const float* time_b    = (const float*)d_in[6];
    const float* Wq        = (const float*)d_in[7];
    const float* bq        = (const float*)d_in[8];
    const float* Wo        = (const float*)d_in[9];
    const float* bo        = (const float*)d_in[10];
    const float* four_wr   = (const float*)d_in[11];
    const float* four_wi   = (const float*)d_in[12];
    const float* conv1     = (const float*)d_in[13];
    const float* conv2     = (const float*)d_in[14];
    const float* norm_w    = (const float*)d_in[15];
    const float* norm_b    = (const float*)d_in[16];
    const float* proj_w    = (const float*)d_in[17];
    const float* proj_b    = (const float*)d_in[18];

    float *gx, *gq, *gt2, *gcat, *gacc;
    __half *pa, *yp, *wq, *wo, *c1, *c2, *tw, *itw;
    cudaGetSymbolAddress((void**)&gx,   g_x);
    cudaGetSymbolAddress((void**)&gq,   g_q);
    cudaGetSymbolAddress((void**)&gt2,  g_t2);
    cudaGetSymbolAddress((void**)&gcat, g_cat);
    cudaGetSymbolAddress((void**)&gacc, g_acc);
    cudaGetSymbolAddress((void**)&pa,   g_pa);
    cudaGetSymbolAddress((void**)&yp,   g_yp);
    cudaGetSymbolAddress((void**)&wq,   g_wq);
    cudaGetSymbolAddress((void**)&wo,   g_wo);
    cudaGetSymbolAddress((void**)&c1,   g_c1);
    cudaGetSymbolAddress((void**)&c2,   g_c2);
    cudaGetSymbolAddress((void**)&tw,   g_tw);
    cudaGetSymbolAddress((void**)&itw,  g_itw);

    const int M = MTOT;   // 32768

    init_tw_k<<<256, 256>>>(tw, itw);
    cvt_k<<<(2*DDIM*DDIM + 255)/256, 256>>>(Wq, wq, 2*DDIM*DDIM);
    cvt_k<<<(2*DDIM*DDIM + 255)/256, 256>>>(Wo, wo, 2*DDIM*DDIM);
    cvt_k<<<(2*DFF*DDIM + 255)/256, 256>>>(conv1, c1, 2*DFF*DDIM);
    cvt_k<<<(2*DDIM*DFF + 255)/256, 256>>>(conv2, c2, 2*DDIM*DFF);

    embed_k<<<dim3(LL, BB), DDIM>>>(x_app, x_time, emb, time_w, time_b, gx, pa);

    dim3 tgrid(16, 16, BB), tblk(32, 8);
    dim3 dgrid(4, 8, BB);
    for (int l = 0; l < 2; l++) {
        const float* bql = bq + (size_t)l * DDIM;
        const float* bol = bo + (size_t)l * DDIM;
        const float* wrl = four_wr + (size_t)l * HH * EE * EE * NMODES;
        const float* wil = four_wi + (size_t)l * HH * EE * EE * NMODES;
        size_t owq = (size_t)l * DDIM * DDIM;
        size_t oc1 = (size_t)l * DFF * DDIM;
        size_t oc2 = (size_t)l * DDIM * DFF;

        // q = x @ Wq^T + bq  (f32 out)
        mg2<0,0,1,0>(pa, wq + owq, bql, nullptr, gq, nullptr, M, 512, 512, 512);
        // qT fp16 plane
        transpose_split_k<<<tgrid, tblk>>>(gq, pa);
        // forward DFT: xs = qT @ TW^T  (Nout=64, f32)
        mg2<0,0,0,0>(pa, tw, nullptr, nullptr, gt2, nullptr, M, 128, 512, 64);
        // complex mode mixing -> fp16 plane [M][64]
        modemix_k<<<dim3(NMODES, HH), 256>>>(gt2, wrl, wil, pa);
        // inverse DFT: foutT = g @ ITW^T (f32)
        mg2<0,0,0,0>(pa, itw, nullptr, nullptr, gq, nullptr, M, 512, 64, 512);
        // fout fp16 plane
        transpose_split_k<<<tgrid, tblk>>>(gq, pa);
        // tmp = fout @ Wo^T + bo + x  (f32)
        mg2<0,1,1,0>(pa, wo + owq, bol, gx, gt2, nullptr, M, 512, 512, 512);
        // x = tmp - movavg(tmp)  (f32 + plane)
        decomp_split_k<<<dgrid, 128>>>(gt2, gx, pa);
        // y = relu(x @ c1^T)  (fp16 plane out)
        mg2<1,0,0,1>(pa, c1 + oc1, nullptr, nullptr, nullptr, yp, M, 2048, 512, 2048);
        // tmp = y @ c2^T + x  (f32)
        mg2<0,1,0,0>(yp, c2 + oc2, nullptr, gx, gt2, nullptr, M, 512, 2048, 512);
        // x = tmp - movavg(tmp)
        decomp_split_k<<<dgrid, 128>>>(gt2, gx, pa);
    }

    layernorm_k<<<dim3(LL, BB), DDIM>>>(gx, norm_w, norm_b, gq);
    zero_acc_k<<<BB, DDIM>>>(gacc);
    partial_sum_k<<<dim3(8, BB), DDIM>>>(gq, gacc);
    lastcat_k<<<BB, DDIM>>>(gq, gacc, time_vecs, gcat);
    gemm_nt_kernel<<<dim3((NAPP + 127) / 128, 1), 256>>>(gcat, proj_w, proj_b,
                                                         (float*)d_out, BB, NAPP, KCAT);
}

// round 7
// speedup vs baseline: 2.2149x; 1.0234x over previous
#include <cuda_runtime.h>
#include <cuda_fp16.h>
#include <math.h>
#include <stdint.h>

// Problem constants
#define BB    64
#define LL    512
#define DDIM  512
#define HH    8
#define EE    64
#define DFF   2048
#define NMODES 32
#define NAPP  10000
#define KCAT  536    // D + 24
#define MTOT  (BB*LL)
#define NPADP 10112  // proj N padded to 79*128
#define KPADP 544    // proj K padded to 17*32
#define TWOPI 6.283185307179586476925286766559

// ---------------------------------------------------------------------------
// Scratch (device globals — no runtime allocation allowed)
// ---------------------------------------------------------------------------
__device__ __align__(128) float g_x [MTOT*DDIM];
__device__ __align__(128) float g_q [MTOT*DDIM];
__device__ __align__(128) float g_t2[MTOT*DDIM];
__device__ __align__(128) float g_acc[BB*DDIM];

// fp16 activation / weight planes
__device__ __align__(128) __half g_pa [MTOT*DDIM];
__device__ __align__(128) __half g_pb [MTOT*DDIM];
__device__ __align__(128) __half g_yp [MTOT*DFF];
__device__ __align__(128) __half g_wq [2*DDIM*DDIM];
__device__ __align__(128) __half g_wo [2*DDIM*DDIM];
__device__ __align__(128) __half g_c1 [2*DFF*DDIM];
__device__ __align__(128) __half g_c2 [2*DDIM*DFF];
__device__ __align__(128) __half g_tw [128*512];      // fwd DFT (padded 128 rows)
__device__ __align__(128) __half g_itw[512*64];       // inv DFT
__device__ __align__(128) __half g_cath[128*KPADP];   // padded cat (fp16)
__device__ __align__(128) __half g_pwh[NPADP*KPADP];  // padded proj weights (fp16)

// ---------------------------------------------------------------------------
// PTX helpers (arch-portable: ldmatrix / mma.sync / cp.async only)
// ---------------------------------------------------------------------------
__device__ __forceinline__ uint32_t smem_u32(const void* p) {
    uint32_t a;
    asm("{ .reg .u64 t; cvta.to.shared.u64 t, %1; cvt.u32.u64 %0, t; }" : "=r"(a) : "l"(p));
    return a;
}
#define CP16(d, s)  asm volatile("cp.async.cg.shared.global [%0], [%1], 16;" :: "r"(d), "l"(s) : "memory")
#define CP_COMMIT() asm volatile("cp.async.commit_group;" ::: "memory")
#define CP_WAIT2()  asm volatile("cp.async.wait_group 2;" ::: "memory")
#define CP_WAIT0()  asm volatile("cp.async.wait_group 0;" ::: "memory")

#define LDSM4(r0, r1, r2, r3, a) \
    asm volatile("ldmatrix.sync.aligned.m8n8.x4.shared.b16 {%0,%1,%2,%3}, [%4];" \
        : "=r"(r0), "=r"(r1), "=r"(r2), "=r"(r3) : "r"(a))

#define MMAF16(c, a0, a1, a2, a3, b0, b1) \
    asm volatile("mma.sync.aligned.m16n8k16.row.col.f32.f16.f16.f32 " \
        "{%0,%1,%2,%3}, {%4,%5,%6,%7}, {%8,%9}, {%0,%1,%2,%3};" \
        : "+f"((c)[0]), "+f"((c)[1]), "+f"((c)[2]), "+f"((c)[3]) \
        : "r"(a0), "r"(a1), "r"(a2), "r"(a3), "r"(b0), "r"(b1))

// ---------------------------------------------------------------------------
// Tensor-core GEMM (fp16 x fp16 -> fp32): C[m,n] = sum_k A[m,k]*B[n,k]
//   Tile 128x128, BK=32, 256 threads, 4-stage cp.async pipeline, 2 CTAs/SM.
//   80B row pitch -> conflict-free ldmatrix. K mult of 32.
// ---------------------------------------------------------------------------
#define MG_PL   (128 * 80)
#define MG_STG  (2 * MG_PL)          // 20480 B (A + B)
#define MG_NSTG 4
#define MG_SMEM (MG_NSTG * MG_STG)   // 81920 B
#define OA 0
#define OB MG_PL

template <int RELU, int ADDC, int BIAS, int OUTPL>
__global__ void __launch_bounds__(256, 2)
mgemm_k(const __half* __restrict__ A, const __half* __restrict__ B,
        const float* __restrict__ bias, const float* __restrict__ Cin,
        float* __restrict__ C, __half* __restrict__ Oh, int K, int Nout, int Mout) {
    extern __shared__ __align__(128) char smem[];
    const uint32_t sb = smem_u32(smem);
    const int tid = threadIdx.x, lane = tid & 31, wid = tid >> 5;
    const int wm = wid & 3, wn = wid >> 2;       // warps 4 x 2
    const int m0 = blockIdx.y * 128, n0 = blockIdx.x * 128;

    float acc[2][8][4];
#pragma unroll
    for (int i = 0; i < 2; i++)
#pragma unroll
        for (int j = 0; j < 8; j++)
#pragma unroll
            for (int t = 0; t < 4; t++) acc[i][j][t] = 0.f;

    const uint32_t a_off = (uint32_t)((wm * 32 + (lane & 7) + ((lane >> 3) & 1) * 8) * 80
                                      + (lane >> 4) * 16);
    const uint32_t b_off = (uint32_t)((wn * 64 + ((lane >> 4) & 1) * 8 + (lane & 7)) * 80
                                      + ((lane >> 3) & 1) * 16);

    const int cr = tid >> 1;                 // 0..127 row
    const int cch = tid & 1;                 // 16B-chunk pair selector
    auto cpAB = [&](int c, int s) {
        const uint32_t base = sb + s * MG_STG;
        const size_t ko = (size_t)c * 32 + cch * 16;
        const uint32_t doff = (uint32_t)(cr * 80 + cch * 32);
        const __half* a0 = A + (size_t)(m0 + cr) * K + ko;
        const __half* b0 = B + (size_t)(n0 + cr) * K + ko;
        CP16(base + OA + doff, a0);   CP16(base + OA + doff + 16, a0 + 8);
        CP16(base + OB + doff, b0);   CP16(base + OB + doff + 16, b0 + 8);
        CP_COMMIT();
    };

    const int NC = K >> 5;
    // prologue: 3 stages in flight (empty commit groups keep group count uniform)
#pragma unroll
    for (int i = 0; i < 3; i++) {
        if (i < NC) cpAB(i, i);
        else        CP_COMMIT();
    }
    for (int c = 0; c < NC; c++) {
        const int s = c & (MG_NSTG - 1);
        CP_WAIT2();                              // stage c complete
        __syncthreads();
        if (c + 3 < NC) cpAB(c + 3, (c + 3) & (MG_NSTG - 1));
        else            CP_COMMIT();
        const uint32_t base = sb + s * MG_STG;
#pragma unroll
        for (int ks = 0; ks < 2; ks++) {
            const uint32_t koff = ks * 32;
            uint32_t a[2][4];
#pragma unroll
            for (int mi = 0; mi < 2; mi++)
                LDSM4(a[mi][0], a[mi][1], a[mi][2], a[mi][3],
                      base + OA + a_off + mi * (16 * 80) + koff);
#pragma unroll
            for (int np = 0; np < 4; np++) {
                uint32_t b[4];
                LDSM4(b[0], b[1], b[2], b[3],
                      base + OB + b_off + np * (16 * 80) + koff);
#pragma unroll
                for (int mi = 0; mi < 2; mi++) {
#pragma unroll
                    for (int t = 0; t < 2; t++) {
                        MMAF16(acc[mi][np * 2 + t], a[mi][0], a[mi][1], a[mi][2], a[mi][3],
                               b[2*t], b[2*t + 1]);
                    }
                }
            }
        }
    }
    CP_WAIT0();   // drain trailing empty groups

    // epilogue
#pragma unroll
    for (int mi = 0; mi < 2; mi++) {
        const int r0 = m0 + wm * 32 + mi * 16 + (lane >> 2);
#pragma unroll
        for (int ni = 0; ni < 8; ni++) {
            const int col = n0 + wn * 64 + ni * 8 + 2 * (lane & 3);
            if (col >= Nout) continue;
            float v00 = acc[mi][ni][0], v01 = acc[mi][ni][1];
            float v10 = acc[mi][ni][2], v11 = acc[mi][ni][3];
            if (BIAS) {
                float2 bv = *(const float2*)&bias[col];
                v00 += bv.x; v01 += bv.y; v10 += bv.x; v11 += bv.y;
            }
            const size_t o0 = (size_t)r0 * Nout + col;
            const size_t o1 = (size_t)(r0 + 8) * Nout + col;
            const bool m0ok = (r0 < Mout), m1ok = (r0 + 8 < Mout);
            if (ADDC) {
                if (m0ok) { float2 c0 = *(const float2*)&Cin[o0]; v00 += c0.x; v01 += c0.y; }
                if (m1ok) { float2 c1 = *(const float2*)&Cin[o1]; v10 += c1.x; v11 += c1.y; }
            }
            if (RELU) {
                v00 = fmaxf(v00, 0.f); v01 = fmaxf(v01, 0.f);
                v10 = fmaxf(v10, 0.f); v11 = fmaxf(v11, 0.f);
            }
            if (OUTPL) {
                __half2 h0, h1;
                h0.x = __float2half_rn(v00); h0.y = __float2half_rn(v01);
                h1.x = __float2half_rn(v10); h1.y = __float2half_rn(v11);
                if (m0ok) *(__half2*)&Oh[o0] = h0;
                if (m1ok) *(__half2*)&Oh[o1] = h1;
            } else {
                if (m0ok) *(float2*)&C[o0] = make_float2(v00, v01);
                if (m1ok) *(float2*)&C[o1] = make_float2(v10, v11);
            }
        }
    }
}

template <int R, int AD, int BI, int OP>
static void mg2(const __half* A, const __half* B, const float* bias,
                const float* Cin, float* C, __half* Oh,
                int M, int Npad, int K, int Nout, int Mout) {
    cudaFuncSetAttribute(mgemm_k<R, AD, BI, OP>,
                         cudaFuncAttributeMaxDynamicSharedMemorySize, MG_SMEM);
    dim3 g(Npad / 128, M / 128);
    mgemm_k<R, AD, BI, OP><<<g, 256, MG_SMEM>>>(A, B, bias, Cin, C, Oh, K, Nout, Mout);
}

// ---------------------------------------------------------------------------
// Weight conversion + twiddle init
// ---------------------------------------------------------------------------
__global__ void cvt_k(const float* __restrict__ s, __half* __restrict__ h, int n) {
    int i = blockIdx.x * blockDim.x + threadIdx.x;
    if (i < n) h[i] = __float2half_rn(s[i]);
}

__global__ void cvt_pad_k(const float* __restrict__ w, __half* __restrict__ o) {
    int i = blockIdx.x * blockDim.x + threadIdx.x;
    if (i < NPADP * KPADP) {
        int r = i / KPADP, c = i - r * KPADP;
        o[i] = (r < NAPP && c < KCAT) ? __float2half_rn(w[(size_t)r * KCAT + c]) : __half(0.f);
    }
}

__global__ void init_tw_k(__half* tw, __half* itw) {
    int i = blockIdx.x * blockDim.x + threadIdx.x;   // 0..65535
    {
        int c = i >> 9, l = i & 511;
        double v = 0.0;
        if (c < 32)       v = cos((TWOPI / 512.0) * (double)(l * c));
        else if (c < 64)  v = -sin((TWOPI / 512.0) * (double)(l * (c - 32)));
        tw[i] = __float2half_rn((float)v);
    }
    if (i < 512 * 64) {
        int l = i >> 6, c = i & 63;
        double v;
        if (c == 0)       v = 1.0 / 512.0;
        else if (c < 32)  v = 2.0 * cos((TWOPI / 512.0) * (double)(l * c)) / 512.0;
        else if (c == 32) v = 0.0;
        else              v = -2.0 * sin((TWOPI / 512.0) * (double)(l * (c - 32))) / 512.0;
        itw[i] = __float2half_rn((float)v);
    }
}

// ---------------------------------------------------------------------------
// Embedding (writes f32 + fp16 plane)
// ---------------------------------------------------------------------------
__global__ void embed_k(const int* __restrict__ x_app, const float* __restrict__ x_time,
                        const float* __restrict__ emb, const float* __restrict__ tw,
                        const float* __restrict__ tb, float* __restrict__ x,
                        __half* __restrict__ pa) {
    int b = blockIdx.y, l = blockIdx.x, d = threadIdx.x;
    int a = x_app[b * LL + l];
    float t = x_time[b * LL + l];
    size_t idx = ((size_t)b * LL + l) * DDIM + d;
    float v = emb[(size_t)a * DDIM + d] + t * tw[d] + tb[d];
    x[idx] = v;
    pa[idx] = __float2half_rn(v);
}

// ---------------------------------------------------------------------------
// Per-batch 512x512 transpose, fp16 -> fp16
// ---------------------------------------------------------------------------
__global__ void transpose_half_k(const __half* __restrict__ in, __half* __restrict__ out) {
    __shared__ __half tile[32][33];
    int b = blockIdx.z;
    const __half* ip = in + (size_t)b * (512 * 512);
    __half* op = out + (size_t)b * (512 * 512);
    int i0 = blockIdx.y * 32, j0 = blockIdx.x * 32;
#pragma unroll
    for (int r = 0; r < 32; r += 8)
        tile[threadIdx.y + r][threadIdx.x] =
            ip[(size_t)(i0 + threadIdx.y + r) * 512 + j0 + threadIdx.x];
    __syncthreads();
#pragma unroll
    for (int r = 0; r < 32; r += 8)
        op[(size_t)(j0 + threadIdx.y + r) * 512 + i0 + threadIdx.x] =
            tile[threadIdx.x][threadIdx.y + r];
}

// ---------------------------------------------------------------------------
// Complex mode mixing -> writes fp16 plane [M][64]
// ---------------------------------------------------------------------------
__global__ void modemix_k(const float* __restrict__ xs, const float* __restrict__ wr,
                          const float* __restrict__ wi, __half* __restrict__ pa) {
    int mode = blockIdx.x, h = blockIdx.y;
    __shared__ float Xr[64][32], Xi[64][32], Wr[32][64], Wi[32][64];
    int tid = threadIdx.x;
    int tb = tid >> 4, to = tid & 15;
    float cr[4][4], ci[4][4];
#pragma unroll
    for (int a = 0; a < 4; a++)
#pragma unroll
        for (int c = 0; c < 4; c++) { cr[a][c] = 0.f; ci[a][c] = 0.f; }
    for (int i0 = 0; i0 < 64; i0 += 32) {
#pragma unroll
        for (int j = 0; j < 8; j++) {
            int e = tid * 8 + j;
            int b = e >> 5, ii = e & 31;
            size_t xrow = ((size_t)b * 512 + h * 64 + i0 + ii) * 64;
            Xr[b][ii] = xs[xrow + mode];
            Xi[b][ii] = xs[xrow + 32 + mode];
            int wi2 = e >> 6, o = e & 63;
            size_t widx = (((size_t)h * 64 + i0 + wi2) * 64 + o) * 32 + mode;
            Wr[wi2][o] = wr[widx];
            Wi[wi2][o] = wi[widx];
        }
        __syncthreads();
#pragma unroll 8
        for (int ii = 0; ii < 32; ii++) {
            float xr[4], xi4[4], wrv[4], wiv[4];
#pragma unroll
            for (int a = 0; a < 4; a++) { xr[a] = Xr[tb*4+a][ii]; xi4[a] = Xi[tb*4+a][ii]; }
#pragma unroll
            for (int c = 0; c < 4; c++) { wrv[c] = Wr[ii][to*4+c]; wiv[c] = Wi[ii][to*4+c]; }
#pragma unroll
            for (int a = 0; a < 4; a++)
#pragma unroll
                for (int c = 0; c < 4; c++) {
                    cr[a][c] += xr[a] * wrv[c] - xi4[a] * wiv[c];
                    ci[a][c] += xr[a] * wiv[c] + xi4[a] * wrv[c];
                }
        }
        __syncthreads();
    }
#pragma unroll
    for (int a = 0; a < 4; a++) {
        int b = tb * 4 + a;
#pragma unroll
        for (int c = 0; c < 4; c++) {
            int o = to * 4 + c;
            size_t base = ((size_t)b * 512 + h * 64 + o) * 64;
            pa[base + mode] = __float2half_rn(cr[a][c]);
            pa[base + 32 + mode] = __float2half_rn(ci[a][c]);
        }
    }
}

// ---------------------------------------------------------------------------
// Series decomposition: rolling 25-window; writes f32 + fp16 plane
// ---------------------------------------------------------------------------
__global__ void decomp_split_k(const float* __restrict__ in, float* __restrict__ out,
                               __half* __restrict__ pa) {
    int b = blockIdx.z;
    int d = blockIdx.x * 128 + threadIdx.x;
    int l0 = blockIdx.y * 64;
    const float* p = in + (size_t)b * (LL * DDIM) + d;
    float sum = 0.f;
#pragma unroll
    for (int j = -12; j <= 12; j++) {
        int t = l0 + j;
        t = t < 0 ? 0 : (t > 511 ? 511 : t);
        sum += p[(size_t)t * DDIM];
    }
    size_t obase = (size_t)b * (LL * DDIM) + d;
    for (int l = l0; l < l0 + 64; l++) {
        float v = p[(size_t)l * DDIM] - sum * (1.0f / 25.0f);
        out[obase + (size_t)l * DDIM] = v;
        pa[obase + (size_t)l * DDIM] = __float2half_rn(v);
        int jn = l + 13 > 511 ? 511 : l + 13;
        int jo = l - 12 < 0 ? 0 : l - 12;
        sum += p[(size_t)jn * DDIM] - p[(size_t)jo * DDIM];
    }
}

// ---------------------------------------------------------------------------
// LayerNorm + parallel last-token concat
// ---------------------------------------------------------------------------
__device__ __forceinline__ float blocksum512(float v, float* red) {
    int lane = threadIdx.x & 31, w = threadIdx.x >> 5;
#pragma unroll
    for (int o = 16; o; o >>= 1) v += __shfl_down_sync(0xffffffffu, v, o);
    if (lane == 0) red[w] = v;
    __syncthreads();
    if (w == 0) {
        float t = (lane < 16) ? red[lane] : 0.f;
#pragma unroll
        for (int o = 8; o; o >>= 1) t += __shfl_down_sync(0xffffffffu, t, o);
        if (lane == 0) red[0] = t;
    }
    __syncthreads();
    float r = red[0];
    __syncthreads();
    return r;
}

__global__ void layernorm_k(const float* __restrict__ x, const float* __restrict__ w,
                            const float* __restrict__ bb, float* __restrict__ xh) {
    __shared__ float red[32];
    int b = blockIdx.y, l = blockIdx.x, d = threadIdx.x;
    size_t base = ((size_t)b * LL + l) * DDIM;
    float v = x[base + d];
    float mu = blocksum512(v, red) * (1.f / 512.f);
    float dv = v - mu;
    float var = blocksum512(dv * dv, red) * (1.f / 512.f);
    xh[base + d] = dv * rsqrtf(var + 1e-5f) * w[d] + bb[d];
}

__global__ void zero_acc_k(float* __restrict__ acc) {
    acc[blockIdx.x * 512 + threadIdx.x] = 0.f;
}

__global__ void zero_cath_k(__half* __restrict__ cath) {
    int i = blockIdx.x * blockDim.x + threadIdx.x;
    if (i < 128 * KPADP) cath[i] = __half(0.f);
}

__global__ void partial_sum_k(const float* __restrict__ xh, float* __restrict__ acc) {
    int b = blockIdx.y, d = threadIdx.x;
    int l0 = blockIdx.x * 64;
    float s = 0.f;
    for (int l = l0; l < l0 + 64; l++) s += xh[((size_t)b * LL + l) * DDIM + d];
    atomicAdd(&acc[b * DDIM + d], s);
}

__global__ void lastcat_k(const float* __restrict__ xh, const float* __restrict__ acc,
                          const float* __restrict__ time_vecs, __half* __restrict__ cath) {
    int b = blockIdx.x, d = threadIdx.x;
    float v = xh[((size_t)b * LL + 511) * DDIM + d] - acc[b * DDIM + d] * (1.f / 512.f);
    cath[b * KPADP + d] = __float2half_rn(v);
    if (d < 24)
        cath[b * KPADP + 512 + d] = __float2half_rn(time_vecs[((size_t)b * LL + 511) * 24 + d]);
}

// ---------------------------------------------------------------------------
// Host orchestration
// ---------------------------------------------------------------------------
extern "C" void kernel_launch(void* const* d_in, const int* in_sizes, int n_in,
                              void* d_out, int out_size) {
    (void)in_sizes; (void)n_in; (void)out_size;
    const int*   x_app     = (const int*)  d_in[0];
    const float* x_time    = (const float*)d_in[1];
    const float* time_vecs = (const float*)d_in[2];
    const float* emb       = (const float*)d_in[4];
    const float* time_w    = (const float*)d_in[5];
    const float* time_b    = (const float*)d_in[6];
    const float* Wq        = (const float*)d_in[7];
    const float* bq        = (const float*)d_in[8];
    const float* Wo        = (const float*)d_in[9];
    const float* bo        = (const float*)d_in[10];
    const float* four_wr   = (const float*)d_in[11];
    const float* four_wi   = (const float*)d_in[12];
    const float* conv1     = (const float*)d_in[13];
    const float* conv2     = (const float*)d_in[14];
    const float* norm_w    = (const float*)d_in[15];
    const float* norm_b    = (const float*)d_in[16];
    const float* proj_w    = (const float*)d_in[17];
    const float* proj_b    = (const float*)d_in[18];

    float *gx, *gq, *gt2, *gacc;
    __half *pa, *pb, *yp, *wq, *wo, *c1, *c2, *tw, *itw, *cath, *pwh;
    cudaGetSymbolAddress((void**)&gx,   g_x);
    cudaGetSymbolAddress((void**)&gq,   g_q);
    cudaGetSymbolAddress((void**)&gt2,  g_t2);
    cudaGetSymbolAddress((void**)&gacc, g_acc);
    cudaGetSymbolAddress((void**)&pa,   g_pa);
    cudaGetSymbolAddress((void**)&pb,   g_pb);
    cudaGetSymbolAddress((void**)&yp,   g_yp);
    cudaGetSymbolAddress((void**)&wq,   g_wq);
    cudaGetSymbolAddress((void**)&wo,   g_wo);
    cudaGetSymbolAddress((void**)&c1,   g_c1);
    cudaGetSymbolAddress((void**)&c2,   g_c2);
    cudaGetSymbolAddress((void**)&tw,   g_tw);
    cudaGetSymbolAddress((void**)&itw,  g_itw);
    cudaGetSymbolAddress((void**)&cath, g_cath);
    cudaGetSymbolAddress((void**)&pwh,  g_pwh);

    const int M = MTOT;   // 32768

    init_tw_k<<<256, 256>>>(tw, itw);
    cvt_k<<<(2*DDIM*DDIM + 255)/256, 256>>>(Wq, wq, 2*DDIM*DDIM);
    cvt_k<<<(2*DDIM*DDIM + 255)/256, 256>>>(Wo, wo, 2*DDIM*DDIM);
    cvt_k<<<(2*DFF*DDIM + 255)/256, 256>>>(conv1, c1, 2*DFF*DDIM);
    cvt_k<<<(2*DDIM*DFF + 255)/256, 256>>>(conv2, c2, 2*DDIM*DFF);
    cvt_pad_k<<<(NPADP*KPADP + 255)/256, 256>>>(proj_w, pwh);

    embed_k<<<dim3(LL, BB), DDIM>>>(x_app, x_time, emb, time_w, time_b, gx, pa);

    dim3 tgrid(16, 16, BB), tblk(32, 8);
    dim3 dgrid(4, 8, BB);
    for (int l = 0; l < 2; l++) {
        const float* bql = bq + (size_t)l * DDIM;
        const float* bol = bo + (size_t)l * DDIM;
        const float* wrl = four_wr + (size_t)l * HH * EE * EE * NMODES;
        const float* wil = four_wi + (size_t)l * HH * EE * EE * NMODES;
        size_t owq = (size_t)l * DDIM * DDIM;
        size_t oc1 = (size_t)l * DFF * DDIM;
        size_t oc2 = (size_t)l * DDIM * DFF;

        // q = x @ Wq^T + bq  (fp16 plane out -> pb)
        mg2<0,0,1,1>(pa, wq + owq, bql, nullptr, nullptr, pb, M, 512, 512, 512, M);
        // qT (fp16): pb -> pa
        transpose_half_k<<<tgrid, tblk>>>(pb, pa);
        // forward DFT: xs = qT @ TW^T  (Nout=64, f32)
        mg2<0,0,0,0>(pa, tw, nullptr, nullptr, gt2, nullptr, M, 128, 512, 64, M);
        // complex mode mixing -> fp16 plane [M][64] (pa)
        modemix_k<<<dim3(NMODES, HH), 256>>>(gt2, wrl, wil, pa);
        // inverse DFT: foutT = g @ ITW^T (fp16 out -> pb)
        mg2<0,0,0,1>(pa, itw, nullptr, nullptr, nullptr, pb, M, 512, 64, 512, M);
        // fout (fp16): pb -> pa
        transpose_half_k<<<tgrid, tblk>>>(pb, pa);
        // tmp = fout @ Wo^T + bo + x  (f32)
        mg2<0,1,1,0>(pa, wo + owq, bol, gx, gt2, nullptr, M, 512, 512, 512, M);
        // x = tmp - movavg(tmp)  (f32 + plane)
        decomp_split_k<<<dgrid, 128>>>(gt2, gx, pa);
        // y = relu(x @ c1^T)  (fp16 plane out)
        mg2<1,0,0,1>(pa, c1 + oc1, nullptr, nullptr, nullptr, yp, M, 2048, 512, 2048, M);
        // tmp = y @ c2^T + x  (f32)
        mg2<0,1,0,0>(yp, c2 + oc2, nullptr, gx, gt2, nullptr, M, 512, 2048, 512, M);
        // x = tmp - movavg(tmp)
        decomp_split_k<<<dgrid, 128>>>(gt2, gx, pa);
    }

    layernorm_k<<<dim3(LL, BB), DDIM>>>(gx, norm_w, norm_b, gq);
    zero_acc_k<<<BB, DDIM>>>(gacc);
    zero_cath_k<<<(128*KPADP + 255)/256, 256>>>(cath);
    partial_sum_k<<<dim3(8, BB), DDIM>>>(gq, gacc);
    lastcat_k<<<BB, DDIM>>>(gq, gacc, time_vecs, cath);
    // score = cat @ proj_w^T + proj_b  (tensor path, Mout=64)
    mg2<0,0,1,0>(cath, pwh, proj_b, nullptr, (float*)d_out, nullptr,
                 128, NPADP, KPADP, NAPP, BB);
}